// round 13
// baseline (speedup 1.0000x reference)
#include <cuda_runtime.h>
#include <cuda_fp16.h>
#include <cstdint>
#include <math.h>

// Problem constants
constexpr int Bc = 2, Sc = 2048, Ec = 1024, Hc = 16, Dc = 64;
constexpr int MROWS = Bc * Sc;  // 4096
constexpr int BH = Bc * Hc;     // 32

// ---------------------------------------------------------------------------
// Scratch (device globals: allocation-free). All plain fp16.
// ---------------------------------------------------------------------------
__device__ __half g_Xp[(size_t)MROWS * Ec];    // x plain fp16 (QKV A)
__device__ __half g_Bp[(size_t)3 * Ec * Ec];   // W_attn^T plain fp16
__device__ __half g_Bp2[(size_t)Ec * Ec];      // W_proj^T plain fp16
__device__ __half g_Yp[(size_t)MROWS * Ec];    // attention out (proj A)
// Attention operands: Q (pre-scaled 1/8), K, V transposed — all plain fp16
__device__ __half g_Qp[(size_t)BH * Sc * Dc];
__device__ __half g_Kp[(size_t)BH * Sc * Dc];
__device__ __half g_Vtp[(size_t)BH * Dc * Sc];

// ---------------------------------------------------------------------------
// PTX helpers (sm_80-class base features — safe under compute_103)
// ---------------------------------------------------------------------------
__device__ __forceinline__ uint32_t smem_to_u32(const void* smem_ptr) {
    uint32_t addr;
    asm("{ .reg .u64 tmp; cvta.to.shared.u64 tmp, %1; cvt.u32.u64 %0, tmp; }"
        : "=r"(addr) : "l"(smem_ptr));
    return addr;
}

__device__ __forceinline__ void cp_async16(uint32_t smem_addr, const void* gptr) {
    asm volatile("cp.async.cg.shared.global [%0], [%1], 16;\n"
                 :: "r"(smem_addr), "l"(gptr));
}
__device__ __forceinline__ void cp_commit() {
    asm volatile("cp.async.commit_group;\n" ::: "memory");
}
template <int N>
__device__ __forceinline__ void cp_wait_group() {
    asm volatile("cp.async.wait_group %0;\n" :: "n"(N) : "memory");
}

__device__ __forceinline__ void ldmatrix_x4(uint32_t* r, uint32_t addr) {
    asm volatile("ldmatrix.sync.aligned.m8n8.x4.shared.b16 {%0,%1,%2,%3}, [%4];"
                 : "=r"(r[0]), "=r"(r[1]), "=r"(r[2]), "=r"(r[3]) : "r"(addr));
}

__device__ __forceinline__ void mma_f16(float* c, const uint32_t* a,
                                        uint32_t b0, uint32_t b1) {
    asm volatile(
        "mma.sync.aligned.m16n8k16.row.col.f32.f16.f16.f32 "
        "{%0,%1,%2,%3}, {%4,%5,%6,%7}, {%8,%9}, {%0,%1,%2,%3};"
        : "+f"(c[0]), "+f"(c[1]), "+f"(c[2]), "+f"(c[3])
        : "r"(a[0]), "r"(a[1]), "r"(a[2]), "r"(a[3]), "r"(b0), "r"(b1));
}

__device__ __forceinline__ uint32_t pack_f16x2_plain(float p0, float p1) {
    __half2 h2 = __floats2half2_rn(p0, p1);   // p0 -> low half
    return *reinterpret_cast<uint32_t*>(&h2);
}

// ---------------------------------------------------------------------------
// Fused prep kernel (convert x + both W transposes in one launch)
// ---------------------------------------------------------------------------
constexpr int NB_CVT = (MROWS * Ec) / 256;          // 16384
constexpr int NB_TA  = (3 * Ec / 32) * (Ec / 32);   // 3072
constexpr int NB_TP  = (Ec / 32) * (Ec / 32);       // 1024

__global__ __launch_bounds__(256)
void prep_kernel(const float* __restrict__ x,
                 const float* __restrict__ W_attn,
                 const float* __restrict__ W_proj,
                 __half* __restrict__ Xp,
                 __half* __restrict__ Bp,
                 __half* __restrict__ Bp2) {
    const int bid = blockIdx.x;
    const int t   = threadIdx.x;
    if (bid < NB_CVT) {
        const int i = bid * 256 + t;
        Xp[i] = __float2half_rn(x[i]);
        return;
    }
    __shared__ float ts[32][33];
    const float* W;
    __half* Bt;
    int K = Ec, N, bx, by;
    if (bid < NB_CVT + NB_TA) {
        const int idx = bid - NB_CVT;
        W = W_attn; Bt = Bp; N = 3 * Ec;
        bx = idx % (3 * Ec / 32); by = idx / (3 * Ec / 32);
    } else {
        const int idx = bid - NB_CVT - NB_TA;
        W = W_proj; Bt = Bp2; N = Ec;
        bx = idx % (Ec / 32); by = idx / (Ec / 32);
    }
    const int k0 = by * 32;
    const int n0 = bx * 32;
    const int tx = t & 31;
    const int ty = t >> 5;
    #pragma unroll
    for (int i = 0; i < 4; i++)
        ts[ty + i * 8][tx] = W[(size_t)(k0 + ty + i * 8) * N + n0 + tx];
    __syncthreads();
    #pragma unroll
    for (int i = 0; i < 4; i++) {
        float v = ts[tx][ty + i * 8];
        Bt[(size_t)(n0 + ty + i * 8) * K + k0 + tx] = __float2half_rn(v);
    }
}

// ---------------------------------------------------------------------------
// HMMA plain-fp16 GEMM (fp32 accumulate), BK=64, 2-stage cp.async.
// WARP-PHASE STAGGER: warps 0-3 iterate ks {0,1,2,3}, warps 4-7 {2,3,0,1} —
// each SMSP's two resident warps are in opposite LDSM/mma phases, breaking
// the post-barrier lockstep that left the tensor pipe at 42%.
// MODE 0: C=fp32 (+bias). MODE 1: QKV-fused epilogue (fp16 Q/K/Vt).
// ---------------------------------------------------------------------------
constexpr int GBM = 128, GBN = 128, GBK = 64;
constexpr int G_PITCH  = 144;
constexpr int G_TILE_B  = 128 * G_PITCH;    // 18432
constexpr int G_STAGE_B = 2 * G_TILE_B;     // 36864
constexpr int GEMM_SMEM = 2 * G_STAGE_B;    // 73728 (>= V-epi 66048)

template <int MODE>
__global__ __launch_bounds__(256, 2)
void gemm_mma_kernel(const __half* __restrict__ Ap,
                     const __half* __restrict__ Bp,
                     const float* __restrict__ bias,
                     float* __restrict__ C,
                     int N, int K,
                     __half* __restrict__ Qp,
                     __half* __restrict__ Kp,
                     __half* __restrict__ Vtp) {
    extern __shared__ __align__(128) char gsm[];
    const uint32_t smb = smem_to_u32(gsm);

    const int tid  = threadIdx.x;
    const int wid  = tid >> 5;
    const int lane = tid & 31;
    const int m0 = blockIdx.y * GBM;
    const int n0 = blockIdx.x * GBN;
    const int wm = (wid & 3) * 32;
    const int wn = (wid >> 2) * 64;
    const int kphase = (wid >> 2) << 1;   // 0 for warps 0-3, 2 for warps 4-7

    const int kiters = K / GBK;  // 16

    float acc[2][8][4] = {};

    const int a_row_off = lane & 15;
    const int a_k_off   = (lane >> 4) * 8;
    const int b_n_off   = ((lane >> 4) & 1) * 8 + (lane & 7);
    const int b_k_off   = ((lane >> 3) & 1) * 8;

    auto issue_load = [&](int it, int stage) {
        const int kc = it * GBK;
        const uint32_t sb = smb + stage * G_STAGE_B;
        #pragma unroll
        for (int c = 0; c < 4; c++) {
            const int chunk = tid + c * 256;
            const int row = chunk >> 3;
            const int c16 = chunk & 7;
            const uint32_t soff = row * G_PITCH + c16 * 16;
            cp_async16(sb + soff,
                       Ap + (size_t)(m0 + row) * K + kc + c16 * 8);
            cp_async16(sb + G_TILE_B + soff,
                       Bp + (size_t)(n0 + row) * K + kc + c16 * 8);
        }
    };

    issue_load(0, 0);
    cp_commit();

    int cur = 0;
    for (int it = 0; it < kiters; it++) {
        if (it + 1 < kiters) {
            issue_load(it + 1, cur ^ 1);
            cp_commit();
            cp_wait_group<1>();
        } else {
            cp_wait_group<0>();
        }
        __syncthreads();

        const uint32_t sb = smb + cur * G_STAGE_B;
        #pragma unroll
        for (int ks0 = 0; ks0 < 4; ks0++) {
            const int ks = (ks0 + kphase) & 3;     // staggered phase
            const int k0 = ks * 16;
            uint32_t af[2][4], bf[4][4];
            #pragma unroll
            for (int mt = 0; mt < 2; mt++) {
                ldmatrix_x4(af[mt], sb
                            + (wm + mt * 16 + a_row_off) * G_PITCH
                            + (k0 + a_k_off) * 2);
            }
            #pragma unroll
            for (int ng = 0; ng < 4; ng++) {
                ldmatrix_x4(bf[ng], sb + G_TILE_B
                            + (wn + ng * 16 + b_n_off) * G_PITCH
                            + (k0 + b_k_off) * 2);
            }
            #pragma unroll
            for (int mt = 0; mt < 2; mt++) {
                #pragma unroll
                for (int ng = 0; ng < 4; ng++) {
                    mma_f16(acc[mt][2*ng],   af[mt], bf[ng][0], bf[ng][1]);
                    mma_f16(acc[mt][2*ng+1], af[mt], bf[ng][2], bf[ng][3]);
                }
            }
        }
        __syncthreads();
        cur ^= 1;
    }

    if (MODE == 0) {
        #pragma unroll
        for (int mt = 0; mt < 2; mt++) {
            const int row = m0 + wm + mt * 16 + (lane >> 2);
            #pragma unroll
            for (int nt = 0; nt < 8; nt++) {
                const int col = n0 + wn + nt * 8 + (lane & 3) * 2;
                const float b0 = bias[col], b1 = bias[col + 1];
                float2 o0 = {acc[mt][nt][0] + b0, acc[mt][nt][1] + b1};
                float2 o1 = {acc[mt][nt][2] + b0, acc[mt][nt][3] + b1};
                *(float2*)(C + (size_t)row * N + col) = o0;
                *(float2*)(C + (size_t)(row + 8) * N + col) = o1;
            }
        }
    } else {
        const int sec = n0 >> 10;        // 0=Q, 1=K, 2=V
        const int b   = m0 >> 11;
        const int s0t = m0 & 2047;
        if (sec < 2) {
            __half* Tp = (sec == 0) ? Qp : Kp;
            const float scale = (sec == 0) ? 0.125f : 1.0f;
            #pragma unroll
            for (int mt = 0; mt < 2; mt++) {
                const int s = s0t + wm + mt * 16 + (lane >> 2);
                #pragma unroll
                for (int nt = 0; nt < 8; nt++) {
                    const int col = n0 + wn + nt * 8 + (lane & 3) * 2;
                    const int e = col & 1023;
                    const int h = e >> 6, d = e & 63;
                    const size_t rowb = (size_t)(b * Hc + h) * Sc;
                    const float bb0 = bias[col], bb1 = bias[col + 1];
                    *(uint32_t*)(Tp + (rowb + s) * Dc + d) =
                        pack_f16x2_plain((acc[mt][nt][0] + bb0) * scale,
                                         (acc[mt][nt][1] + bb1) * scale);
                    *(uint32_t*)(Tp + (rowb + s + 8) * Dc + d) =
                        pack_f16x2_plain((acc[mt][nt][2] + bb0) * scale,
                                         (acc[mt][nt][3] + bb1) * scale);
                }
            }
        } else {
            float* smT = (float*)gsm;
            #pragma unroll
            for (int mt = 0; mt < 2; mt++) {
                const int r = wm + mt * 16 + (lane >> 2);
                #pragma unroll
                for (int nt = 0; nt < 8; nt++) {
                    const int c = wn + nt * 8 + (lane & 3) * 2;
                    const int col = n0 + c;
                    const float bb0 = bias[col], bb1 = bias[col + 1];
                    smT[r * 129 + c]           = acc[mt][nt][0] + bb0;
                    smT[r * 129 + c + 1]       = acc[mt][nt][1] + bb1;
                    smT[(r + 8) * 129 + c]     = acc[mt][nt][2] + bb0;
                    smT[(r + 8) * 129 + c + 1] = acc[mt][nt][3] + bb1;
                }
            }
            __syncthreads();
            const int c  = tid & 127;
            const int sh = (tid >> 7) * 64;
            const int e  = (n0 + c) & 1023;
            const int h  = e >> 6, d = e & 63;
            const size_t vbase = ((size_t)(b * Hc + h) * Dc + d) * Sc + s0t + sh;
            #pragma unroll
            for (int s = 0; s < 64; s += 2) {
                *(uint32_t*)(Vtp + vbase + s) =
                    pack_f16x2_plain(smT[(sh + s) * 129 + c],
                                     smT[(sh + s + 1) * 129 + c]);
            }
        }
    }
}

// ---------------------------------------------------------------------------
// Tensor-core causal flash attention, all plain fp16 (fp32 accumulate).
// Q-TILE PAIRING (balanced single wave) + warp-parity stagger on the
// QK ks-loop and PV j-loop to spread SM-wide LDSM crossbar bursts.
// ---------------------------------------------------------------------------
constexpr int AT_ROW = 144;
constexpr int AT_TILE_B = 64 * AT_ROW;         // 9216
constexpr int ATT_SMEM_BYTES = 5 * AT_TILE_B;  // 46080

__global__ __launch_bounds__(128, 4)
void attn_mma_kernel(const __half* __restrict__ Qp,
                     const __half* __restrict__ Kp,
                     const __half* __restrict__ Vtp,
                     __half* __restrict__ Yp) {
    extern __shared__ __half smf[];
    const uint32_t smb = smem_to_u32(smf);

    const int bh = blockIdx.y;
    const int b  = bh >> 4;
    const int h  = bh & 15;
    const int tid  = threadIdx.x;
    const int wid  = tid >> 5;
    const int lane = tid & 31;
    const int wm   = wid * 16;
    const int kph  = (wid & 1) << 1;   // stagger phase 0 / 2

    const size_t bhQK = (size_t)bh * Sc * Dc;
    const size_t bhVT = (size_t)bh * Dc * Sc;

    const uint32_t sQ_a = smb;
    auto stage_addr = [&](int buf, int t) -> uint32_t {
        return smb + (1 + buf * 2 + t) * AT_TILE_B;
    };

    auto load_qk_tile = [&](uint32_t sa, const __half* src, int s0) {
        #pragma unroll
        for (int i = 0; i < 4; i++) {
            const int idx = tid + i * 128;
            const int row = idx >> 3;
            const int c16 = idx & 7;
            cp_async16(sa + row * AT_ROW + c16 * 16,
                       src + bhQK + (size_t)(s0 + row) * Dc + c16 * 8);
        }
    };
    auto load_vt_tile = [&](uint32_t sa, const __half* src, int kb) {
        #pragma unroll
        for (int i = 0; i < 4; i++) {
            const int idx = tid + i * 128;
            const int row = idx >> 3;
            const int c16 = idx & 7;
            cp_async16(sa + row * AT_ROW + c16 * 16,
                       src + bhVT + (size_t)row * Sc + kb + c16 * 8);
        }
    };
    auto issue_stage = [&](int t, int buf) {
        const int kb = t * 64;
        load_qk_tile(stage_addr(buf, 0), Kp, kb);
        load_vt_tile(stage_addr(buf, 1), Vtp, kb);
    };

    const int a_row_off = lane & 15;
    const int a_k_off   = (lane >> 4) * 8;
    const int b_n_off   = ((lane >> 4) & 1) * 8 + (lane & 7);
    const int b_k_off   = ((lane >> 3) & 1) * 8;

    #pragma unroll 1
    for (int qi = 0; qi < 2; qi++) {
        const int qt = (qi == 0) ? (2 * gridDim.x - 1 - blockIdx.x)
                                 : blockIdx.x;
        const int q0 = qt * 64;
        const int T = qt + 1;

        load_qk_tile(sQ_a, Qp, q0);
        issue_stage(0, 0);
        cp_commit();
        if (T > 1) issue_stage(1, 1);
        cp_commit();

        uint32_t qf[4][4];
        float oacc[8][4] = {};
        float sum_lo = 0.f, sum_hi = 0.f;

        int cur = 0;
        for (int t = 0; t < T; t++) {
            if (t == 0) {
                cp_wait_group<1>();
                __syncthreads();
                #pragma unroll
                for (int ks = 0; ks < 4; ks++) {
                    ldmatrix_x4(qf[ks],
                        sQ_a + (wm + a_row_off) * AT_ROW
                             + (ks * 16 + a_k_off) * 2);
                }
            } else if (t + 1 < T) {
                cp_wait_group<1>();
                __syncthreads();
            } else {
                cp_wait_group<0>();
                __syncthreads();
            }

            const uint32_t sK = stage_addr(cur, 0);
            const uint32_t sV = stage_addr(cur, 1);

            // ---- QK^T (staggered ks) ----
            float sacc[8][4] = {};
            #pragma unroll
            for (int ks0 = 0; ks0 < 4; ks0++) {
                const int ks = (ks0 + kph) & 3;
                uint32_t kf[4][4];
                #pragma unroll
                for (int ng = 0; ng < 4; ng++) {
                    ldmatrix_x4(kf[ng],
                        sK + (ng * 16 + b_n_off) * AT_ROW
                           + (ks * 16 + b_k_off) * 2);
                }
                #pragma unroll
                for (int ng = 0; ng < 4; ng++) {
                    mma_f16(sacc[2*ng],   qf[ks], kf[ng][0], kf[ng][1]);
                    mma_f16(sacc[2*ng+1], qf[ks], kf[ng][2], kf[ng][3]);
                }
            }

            // ---- causal mask (diagonal tile only) + exp + rowsum ----
            if (t == T - 1) {
                const int rlo = wm + (lane >> 2);
                #pragma unroll
                for (int nt = 0; nt < 8; nt++) {
                    const int c = nt * 8 + (lane & 3) * 2;
                    if (c > rlo)         sacc[nt][0] = -1e30f;
                    if (c + 1 > rlo)     sacc[nt][1] = -1e30f;
                    if (c > rlo + 8)     sacc[nt][2] = -1e30f;
                    if (c + 1 > rlo + 8) sacc[nt][3] = -1e30f;
                }
            }
            #pragma unroll
            for (int nt = 0; nt < 8; nt++) {
                sacc[nt][0] = __expf(sacc[nt][0]);
                sacc[nt][1] = __expf(sacc[nt][1]);
                sacc[nt][2] = __expf(sacc[nt][2]);
                sacc[nt][3] = __expf(sacc[nt][3]);
                sum_lo += sacc[nt][0] + sacc[nt][1];
                sum_hi += sacc[nt][2] + sacc[nt][3];
            }

            // ---- P·V (staggered j) ----
            #pragma unroll
            for (int j0 = 0; j0 < 4; j0++) {
                const int j = (j0 + kph) & 3;
                uint32_t ap[4];
                ap[0] = pack_f16x2_plain(sacc[2*j][0],   sacc[2*j][1]);
                ap[1] = pack_f16x2_plain(sacc[2*j][2],   sacc[2*j][3]);
                ap[2] = pack_f16x2_plain(sacc[2*j+1][0], sacc[2*j+1][1]);
                ap[3] = pack_f16x2_plain(sacc[2*j+1][2], sacc[2*j+1][3]);
                #pragma unroll
                for (int ng = 0; ng < 4; ng++) {
                    uint32_t vf[4];
                    ldmatrix_x4(vf,
                        sV + (ng * 16 + b_n_off) * AT_ROW
                           + (j * 16 + b_k_off) * 2);
                    mma_f16(oacc[2*ng],   ap, vf[0], vf[1]);
                    mma_f16(oacc[2*ng+1], ap, vf[2], vf[3]);
                }
            }

            __syncthreads();
            if (t + 2 < T) {
                issue_stage(t + 2, cur);
                cp_commit();
            } else if (t + 1 < T) {
                cp_commit();
            }
            cur ^= 1;
        }

        // ---- epilogue ----
        sum_lo += __shfl_xor_sync(0xFFFFFFFFu, sum_lo, 1);
        sum_lo += __shfl_xor_sync(0xFFFFFFFFu, sum_lo, 2);
        sum_hi += __shfl_xor_sync(0xFFFFFFFFu, sum_hi, 1);
        sum_hi += __shfl_xor_sync(0xFFFFFFFFu, sum_hi, 2);
        const float inv_lo = 1.0f / sum_lo;
        const float inv_hi = 1.0f / sum_hi;

        const int row_lo = q0 + wm + (lane >> 2);
        #pragma unroll
        for (int nt = 0; nt < 8; nt++) {
            const int d = nt * 8 + (lane & 3) * 2;
            const size_t off0 = (size_t)(b * Sc + row_lo) * Ec + h * Dc + d;
            const size_t off1 = off0 + (size_t)8 * Ec;
            *(uint32_t*)(Yp + off0) =
                pack_f16x2_plain(oacc[nt][0] * inv_lo, oacc[nt][1] * inv_lo);
            *(uint32_t*)(Yp + off1) =
                pack_f16x2_plain(oacc[nt][2] * inv_hi, oacc[nt][3] * inv_hi);
        }
    }
}

// ---------------------------------------------------------------------------
extern "C" void kernel_launch(void* const* d_in, const int* in_sizes, int n_in,
                              void* d_out, int out_size) {
    const float* x      = (const float*)d_in[0];
    const float* W_attn = (const float*)d_in[1];
    const float* b_attn = (const float*)d_in[2];
    const float* W_proj = (const float*)d_in[3];
    const float* b_proj = (const float*)d_in[4];
    float* out = (float*)d_out;

    __half *Xp, *Bp, *Bp2, *Yp, *Qp, *Kp, *Vtp;
    cudaGetSymbolAddress((void**)&Xp, g_Xp);
    cudaGetSymbolAddress((void**)&Bp, g_Bp);
    cudaGetSymbolAddress((void**)&Bp2, g_Bp2);
    cudaGetSymbolAddress((void**)&Yp, g_Yp);
    cudaGetSymbolAddress((void**)&Qp, g_Qp);
    cudaGetSymbolAddress((void**)&Kp, g_Kp);
    cudaGetSymbolAddress((void**)&Vtp, g_Vtp);

    cudaFuncSetAttribute(gemm_mma_kernel<0>,
                         cudaFuncAttributeMaxDynamicSharedMemorySize, GEMM_SMEM);
    cudaFuncSetAttribute(gemm_mma_kernel<1>,
                         cudaFuncAttributeMaxDynamicSharedMemorySize, GEMM_SMEM);
    cudaFuncSetAttribute(attn_mma_kernel,
                         cudaFuncAttributeMaxDynamicSharedMemorySize,
                         ATT_SMEM_BYTES);

    // 1) fused prep
    {
        prep_kernel<<<NB_CVT + NB_TA + NB_TP, 256>>>(x, W_attn, W_proj,
                                                     Xp, Bp, Bp2);
    }
    // 2) QKV GEMM, fused epilogue -> attention operands
    {
        dim3 grid(3 * Ec / GBN, MROWS / GBM);
        gemm_mma_kernel<1><<<grid, 256, GEMM_SMEM>>>(Xp, Bp, b_attn,
                                                     nullptr, 3 * Ec, Ec,
                                                     Qp, Kp, Vtp);
    }
    // 3) attention (paired q-tiles, balanced single wave) -> fp16 Yp
    {
        dim3 grid(Sc / 128, BH);  // (16, 32)
        attn_mma_kernel<<<grid, 128, ATT_SMEM_BYTES>>>(Qp, Kp, Vtp, Yp);
    }
    // 4) Proj GEMM -> fp32 out
    {
        dim3 grid(Ec / GBN, MROWS / GBM);
        gemm_mma_kernel<0><<<grid, 256, GEMM_SMEM>>>(Yp, Bp2, b_proj,
                                                     out, Ec, Ec,
                                                     nullptr, nullptr, nullptr);
    }
}

// round 14
// speedup vs baseline: 1.2727x; 1.2727x over previous
#include <cuda_runtime.h>
#include <cuda_fp16.h>
#include <cstdint>
#include <math.h>

// Problem constants
constexpr int Bc = 2, Sc = 2048, Ec = 1024, Hc = 16, Dc = 64;
constexpr int MROWS = Bc * Sc;  // 4096
constexpr int BH = Bc * Hc;     // 32

// ---------------------------------------------------------------------------
// Scratch (device globals: allocation-free). All plain fp16.
// ---------------------------------------------------------------------------
__device__ __half g_Xp[(size_t)MROWS * Ec];    // x plain fp16 (QKV A)
__device__ __half g_Bp[(size_t)3 * Ec * Ec];   // W_attn^T plain fp16
__device__ __half g_Bp2[(size_t)Ec * Ec];      // W_proj^T plain fp16
__device__ __half g_Yp[(size_t)MROWS * Ec];    // attention out (proj A)
// Attention operands: Q (pre-scaled 1/8), K, V transposed — all plain fp16
__device__ __half g_Qp[(size_t)BH * Sc * Dc];
__device__ __half g_Kp[(size_t)BH * Sc * Dc];
__device__ __half g_Vtp[(size_t)BH * Dc * Sc];

// ---------------------------------------------------------------------------
// PTX helpers (sm_80-class base features — safe under compute_103)
// ---------------------------------------------------------------------------
__device__ __forceinline__ uint32_t smem_to_u32(const void* smem_ptr) {
    uint32_t addr;
    asm("{ .reg .u64 tmp; cvta.to.shared.u64 tmp, %1; cvt.u32.u64 %0, tmp; }"
        : "=r"(addr) : "l"(smem_ptr));
    return addr;
}

__device__ __forceinline__ void cp_async16(uint32_t smem_addr, const void* gptr) {
    asm volatile("cp.async.cg.shared.global [%0], [%1], 16;\n"
                 :: "r"(smem_addr), "l"(gptr));
}
__device__ __forceinline__ void cp_commit() {
    asm volatile("cp.async.commit_group;\n" ::: "memory");
}
template <int N>
__device__ __forceinline__ void cp_wait_group() {
    asm volatile("cp.async.wait_group %0;\n" :: "n"(N) : "memory");
}

__device__ __forceinline__ void ldmatrix_x4(uint32_t* r, uint32_t addr) {
    asm volatile("ldmatrix.sync.aligned.m8n8.x4.shared.b16 {%0,%1,%2,%3}, [%4];"
                 : "=r"(r[0]), "=r"(r[1]), "=r"(r[2]), "=r"(r[3]) : "r"(addr));
}

__device__ __forceinline__ void mma_f16(float* c, const uint32_t* a,
                                        uint32_t b0, uint32_t b1) {
    asm volatile(
        "mma.sync.aligned.m16n8k16.row.col.f32.f16.f16.f32 "
        "{%0,%1,%2,%3}, {%4,%5,%6,%7}, {%8,%9}, {%0,%1,%2,%3};"
        : "+f"(c[0]), "+f"(c[1]), "+f"(c[2]), "+f"(c[3])
        : "r"(a[0]), "r"(a[1]), "r"(a[2]), "r"(a[3]), "r"(b0), "r"(b1));
}

__device__ __forceinline__ uint32_t pack_f16x2_plain(float p0, float p1) {
    __half2 h2 = __floats2half2_rn(p0, p1);   // p0 -> low half
    return *reinterpret_cast<uint32_t*>(&h2);
}

// ---------------------------------------------------------------------------
// Fused prep kernel (convert x + both W transposes in one launch)
// ---------------------------------------------------------------------------
constexpr int NB_CVT = (MROWS * Ec) / 256;          // 16384
constexpr int NB_TA  = (3 * Ec / 32) * (Ec / 32);   // 3072
constexpr int NB_TP  = (Ec / 32) * (Ec / 32);       // 1024

__global__ __launch_bounds__(256)
void prep_kernel(const float* __restrict__ x,
                 const float* __restrict__ W_attn,
                 const float* __restrict__ W_proj,
                 __half* __restrict__ Xp,
                 __half* __restrict__ Bp,
                 __half* __restrict__ Bp2) {
    const int bid = blockIdx.x;
    const int t   = threadIdx.x;
    if (bid < NB_CVT) {
        const int i = bid * 256 + t;
        Xp[i] = __float2half_rn(x[i]);
        return;
    }
    __shared__ float ts[32][33];
    const float* W;
    __half* Bt;
    int K = Ec, N, bx, by;
    if (bid < NB_CVT + NB_TA) {
        const int idx = bid - NB_CVT;
        W = W_attn; Bt = Bp; N = 3 * Ec;
        bx = idx % (3 * Ec / 32); by = idx / (3 * Ec / 32);
    } else {
        const int idx = bid - NB_CVT - NB_TA;
        W = W_proj; Bt = Bp2; N = Ec;
        bx = idx % (Ec / 32); by = idx / (Ec / 32);
    }
    const int k0 = by * 32;
    const int n0 = bx * 32;
    const int tx = t & 31;
    const int ty = t >> 5;
    #pragma unroll
    for (int i = 0; i < 4; i++)
        ts[ty + i * 8][tx] = W[(size_t)(k0 + ty + i * 8) * N + n0 + tx];
    __syncthreads();
    #pragma unroll
    for (int i = 0; i < 4; i++) {
        float v = ts[tx][ty + i * 8];
        Bt[(size_t)(n0 + ty + i * 8) * K + k0 + tx] = __float2half_rn(v);
    }
}

// ---------------------------------------------------------------------------
// HMMA plain-fp16 GEMM (fp32 accumulate), BK=64.
// 3-STAGE cp.async pipeline, ONE barrier per iteration: with 3 stages, the
// stage overwritten at iter it was last read at it-1, and the top barrier of
// iter it proves all warps finished it-1's compute. Accumulation order is
// unchanged vs the 2-stage version (bitwise-identical output).
// MODE 0: C=fp32 (+bias). MODE 1: QKV-fused epilogue (fp16 Q/K/Vt).
// ---------------------------------------------------------------------------
constexpr int GBM = 128, GBN = 128, GBK = 64;
constexpr int G_PITCH  = 144;
constexpr int G_TILE_B  = 128 * G_PITCH;    // 18432
constexpr int G_STAGE_B = 2 * G_TILE_B;     // 36864 (A + B)
constexpr int GEMM_SMEM = 3 * G_STAGE_B;    // 110592 (>= V-epi 66048)

template <int MODE>
__global__ __launch_bounds__(256, 2)
void gemm_mma_kernel(const __half* __restrict__ Ap,
                     const __half* __restrict__ Bp,
                     const float* __restrict__ bias,
                     float* __restrict__ C,
                     int N, int K,
                     __half* __restrict__ Qp,
                     __half* __restrict__ Kp,
                     __half* __restrict__ Vtp) {
    extern __shared__ __align__(128) char gsm[];
    const uint32_t smb = smem_to_u32(gsm);

    const int tid  = threadIdx.x;
    const int wid  = tid >> 5;
    const int lane = tid & 31;
    const int m0 = blockIdx.y * GBM;
    const int n0 = blockIdx.x * GBN;
    const int wm = (wid & 3) * 32;
    const int wn = (wid >> 2) * 64;

    const int kiters = K / GBK;  // 16

    float acc[2][8][4] = {};

    const int a_row_off = lane & 15;
    const int a_k_off   = (lane >> 4) * 8;
    const int b_n_off   = ((lane >> 4) & 1) * 8 + (lane & 7);
    const int b_k_off   = ((lane >> 3) & 1) * 8;

    auto issue_load = [&](int it, int stage) {
        const int kc = it * GBK;
        const uint32_t sb = smb + stage * G_STAGE_B;
        #pragma unroll
        for (int c = 0; c < 4; c++) {
            const int chunk = tid + c * 256;
            const int row = chunk >> 3;
            const int c16 = chunk & 7;
            const uint32_t soff = row * G_PITCH + c16 * 16;
            cp_async16(sb + soff,
                       Ap + (size_t)(m0 + row) * K + kc + c16 * 8);
            cp_async16(sb + G_TILE_B + soff,
                       Bp + (size_t)(n0 + row) * K + kc + c16 * 8);
        }
    };

    issue_load(0, 0);
    cp_commit();
    issue_load(1, 1);
    cp_commit();

    int cur = 0;   // stage for iteration it (it % 3)
    for (int it = 0; it < kiters; it++) {
        if (it + 1 < kiters) {
            cp_wait_group<1>();   // completes group for iteration it
        } else {
            cp_wait_group<0>();
        }
        __syncthreads();          // also: all warps done reading stage cur-1

        if (it + 2 < kiters) {
            int nxt = cur + 2;
            if (nxt >= 3) nxt -= 3;
            issue_load(it + 2, nxt);
            cp_commit();
        }

        const uint32_t sb = smb + cur * G_STAGE_B;
        #pragma unroll
        for (int ks = 0; ks < 4; ks++) {
            const int k0 = ks * 16;
            uint32_t af[2][4], bf[4][4];
            #pragma unroll
            for (int mt = 0; mt < 2; mt++) {
                ldmatrix_x4(af[mt], sb
                            + (wm + mt * 16 + a_row_off) * G_PITCH
                            + (k0 + a_k_off) * 2);
            }
            #pragma unroll
            for (int ng = 0; ng < 4; ng++) {
                ldmatrix_x4(bf[ng], sb + G_TILE_B
                            + (wn + ng * 16 + b_n_off) * G_PITCH
                            + (k0 + b_k_off) * 2);
            }
            #pragma unroll
            for (int mt = 0; mt < 2; mt++) {
                #pragma unroll
                for (int ng = 0; ng < 4; ng++) {
                    mma_f16(acc[mt][2*ng],   af[mt], bf[ng][0], bf[ng][1]);
                    mma_f16(acc[mt][2*ng+1], af[mt], bf[ng][2], bf[ng][3]);
                }
            }
        }
        // no bottom barrier (3-stage safety argument above)
        cur++;
        if (cur >= 3) cur = 0;
    }
    __syncthreads();  // protect epilogue smem reuse (V path) + exit coherence

    if (MODE == 0) {
        #pragma unroll
        for (int mt = 0; mt < 2; mt++) {
            const int row = m0 + wm + mt * 16 + (lane >> 2);
            #pragma unroll
            for (int nt = 0; nt < 8; nt++) {
                const int col = n0 + wn + nt * 8 + (lane & 3) * 2;
                const float b0 = bias[col], b1 = bias[col + 1];
                float2 o0 = {acc[mt][nt][0] + b0, acc[mt][nt][1] + b1};
                float2 o1 = {acc[mt][nt][2] + b0, acc[mt][nt][3] + b1};
                *(float2*)(C + (size_t)row * N + col) = o0;
                *(float2*)(C + (size_t)(row + 8) * N + col) = o1;
            }
        }
    } else {
        const int sec = n0 >> 10;        // 0=Q, 1=K, 2=V
        const int b   = m0 >> 11;
        const int s0t = m0 & 2047;
        if (sec < 2) {
            __half* Tp = (sec == 0) ? Qp : Kp;
            const float scale = (sec == 0) ? 0.125f : 1.0f;
            #pragma unroll
            for (int mt = 0; mt < 2; mt++) {
                const int s = s0t + wm + mt * 16 + (lane >> 2);
                #pragma unroll
                for (int nt = 0; nt < 8; nt++) {
                    const int col = n0 + wn + nt * 8 + (lane & 3) * 2;
                    const int e = col & 1023;
                    const int h = e >> 6, d = e & 63;
                    const size_t rowb = (size_t)(b * Hc + h) * Sc;
                    const float bb0 = bias[col], bb1 = bias[col + 1];
                    *(uint32_t*)(Tp + (rowb + s) * Dc + d) =
                        pack_f16x2_plain((acc[mt][nt][0] + bb0) * scale,
                                         (acc[mt][nt][1] + bb1) * scale);
                    *(uint32_t*)(Tp + (rowb + s + 8) * Dc + d) =
                        pack_f16x2_plain((acc[mt][nt][2] + bb0) * scale,
                                         (acc[mt][nt][3] + bb1) * scale);
                }
            }
        } else {
            // V: fp32+bias staged in smem [128][129], transposed fp16 writes
            float* smT = (float*)gsm;
            #pragma unroll
            for (int mt = 0; mt < 2; mt++) {
                const int r = wm + mt * 16 + (lane >> 2);
                #pragma unroll
                for (int nt = 0; nt < 8; nt++) {
                    const int c = wn + nt * 8 + (lane & 3) * 2;
                    const int col = n0 + c;
                    const float bb0 = bias[col], bb1 = bias[col + 1];
                    smT[r * 129 + c]           = acc[mt][nt][0] + bb0;
                    smT[r * 129 + c + 1]       = acc[mt][nt][1] + bb1;
                    smT[(r + 8) * 129 + c]     = acc[mt][nt][2] + bb0;
                    smT[(r + 8) * 129 + c + 1] = acc[mt][nt][3] + bb1;
                }
            }
            __syncthreads();
            const int c  = tid & 127;
            const int sh = (tid >> 7) * 64;
            const int e  = (n0 + c) & 1023;
            const int h  = e >> 6, d = e & 63;
            const size_t vbase = ((size_t)(b * Hc + h) * Dc + d) * Sc + s0t + sh;
            #pragma unroll
            for (int s = 0; s < 64; s += 2) {
                *(uint32_t*)(Vtp + vbase + s) =
                    pack_f16x2_plain(smT[(sh + s) * 129 + c],
                                     smT[(sh + s + 1) * 129 + c]);
            }
        }
    }
}

// ---------------------------------------------------------------------------
// Tensor-core causal flash attention, all plain fp16 (fp32 accumulate).
// Round-12 form (no stagger — that regressed via register spills).
// Q-TILE PAIRING: CTA bx processes q-tiles {2*Gx-1-bx, bx}; every CTA does
// exactly 2*Gx+1 ktiles -> one perfectly balanced wave (512 CTAs, 4/SM).
// ---------------------------------------------------------------------------
constexpr int AT_ROW = 144;
constexpr int AT_TILE_B = 64 * AT_ROW;         // 9216
constexpr int ATT_SMEM_BYTES = 5 * AT_TILE_B;  // 46080

__global__ __launch_bounds__(128, 4)
void attn_mma_kernel(const __half* __restrict__ Qp,
                     const __half* __restrict__ Kp,
                     const __half* __restrict__ Vtp,
                     __half* __restrict__ Yp) {
    extern __shared__ __half smf[];
    const uint32_t smb = smem_to_u32(smf);

    const int bh = blockIdx.y;
    const int b  = bh >> 4;
    const int h  = bh & 15;
    const int tid  = threadIdx.x;
    const int wid  = tid >> 5;
    const int lane = tid & 31;
    const int wm   = wid * 16;

    const size_t bhQK = (size_t)bh * Sc * Dc;
    const size_t bhVT = (size_t)bh * Dc * Sc;

    const uint32_t sQ_a = smb;
    auto stage_addr = [&](int buf, int t) -> uint32_t {
        return smb + (1 + buf * 2 + t) * AT_TILE_B;
    };

    auto load_qk_tile = [&](uint32_t sa, const __half* src, int s0) {
        #pragma unroll
        for (int i = 0; i < 4; i++) {
            const int idx = tid + i * 128;
            const int row = idx >> 3;
            const int c16 = idx & 7;
            cp_async16(sa + row * AT_ROW + c16 * 16,
                       src + bhQK + (size_t)(s0 + row) * Dc + c16 * 8);
        }
    };
    auto load_vt_tile = [&](uint32_t sa, const __half* src, int kb) {
        #pragma unroll
        for (int i = 0; i < 4; i++) {
            const int idx = tid + i * 128;
            const int row = idx >> 3;
            const int c16 = idx & 7;
            cp_async16(sa + row * AT_ROW + c16 * 16,
                       src + bhVT + (size_t)row * Sc + kb + c16 * 8);
        }
    };
    auto issue_stage = [&](int t, int buf) {
        const int kb = t * 64;
        load_qk_tile(stage_addr(buf, 0), Kp, kb);
        load_vt_tile(stage_addr(buf, 1), Vtp, kb);
    };

    const int a_row_off = lane & 15;
    const int a_k_off   = (lane >> 4) * 8;
    const int b_n_off   = ((lane >> 4) & 1) * 8 + (lane & 7);
    const int b_k_off   = ((lane >> 3) & 1) * 8;

    #pragma unroll 1
    for (int qi = 0; qi < 2; qi++) {
        const int qt = (qi == 0) ? (2 * gridDim.x - 1 - blockIdx.x)
                                 : blockIdx.x;
        const int q0 = qt * 64;
        const int T = qt + 1;

        load_qk_tile(sQ_a, Qp, q0);
        issue_stage(0, 0);
        cp_commit();
        if (T > 1) issue_stage(1, 1);
        cp_commit();

        uint32_t qf[4][4];
        float oacc[8][4] = {};
        float sum_lo = 0.f, sum_hi = 0.f;

        int cur = 0;
        for (int t = 0; t < T; t++) {
            if (t == 0) {
                cp_wait_group<1>();
                __syncthreads();
                #pragma unroll
                for (int ks = 0; ks < 4; ks++) {
                    ldmatrix_x4(qf[ks],
                        sQ_a + (wm + a_row_off) * AT_ROW
                             + (ks * 16 + a_k_off) * 2);
                }
            } else if (t + 1 < T) {
                cp_wait_group<1>();
                __syncthreads();
            } else {
                cp_wait_group<0>();
                __syncthreads();
            }

            const uint32_t sK = stage_addr(cur, 0);
            const uint32_t sV = stage_addr(cur, 1);

            // ---- QK^T ----
            float sacc[8][4] = {};
            #pragma unroll
            for (int ks = 0; ks < 4; ks++) {
                uint32_t kf[4][4];
                #pragma unroll
                for (int ng = 0; ng < 4; ng++) {
                    ldmatrix_x4(kf[ng],
                        sK + (ng * 16 + b_n_off) * AT_ROW
                           + (ks * 16 + b_k_off) * 2);
                }
                #pragma unroll
                for (int ng = 0; ng < 4; ng++) {
                    mma_f16(sacc[2*ng],   qf[ks], kf[ng][0], kf[ng][1]);
                    mma_f16(sacc[2*ng+1], qf[ks], kf[ng][2], kf[ng][3]);
                }
            }

            // ---- causal mask (diagonal tile only) + exp + rowsum ----
            if (t == T - 1) {
                const int rlo = wm + (lane >> 2);
                #pragma unroll
                for (int nt = 0; nt < 8; nt++) {
                    const int c = nt * 8 + (lane & 3) * 2;
                    if (c > rlo)         sacc[nt][0] = -1e30f;
                    if (c + 1 > rlo)     sacc[nt][1] = -1e30f;
                    if (c > rlo + 8)     sacc[nt][2] = -1e30f;
                    if (c + 1 > rlo + 8) sacc[nt][3] = -1e30f;
                }
            }
            #pragma unroll
            for (int nt = 0; nt < 8; nt++) {
                sacc[nt][0] = __expf(sacc[nt][0]);
                sacc[nt][1] = __expf(sacc[nt][1]);
                sacc[nt][2] = __expf(sacc[nt][2]);
                sacc[nt][3] = __expf(sacc[nt][3]);
                sum_lo += sacc[nt][0] + sacc[nt][1];
                sum_hi += sacc[nt][2] + sacc[nt][3];
            }

            // ---- P·V ----
            #pragma unroll
            for (int j = 0; j < 4; j++) {
                uint32_t ap[4];
                ap[0] = pack_f16x2_plain(sacc[2*j][0],   sacc[2*j][1]);
                ap[1] = pack_f16x2_plain(sacc[2*j][2],   sacc[2*j][3]);
                ap[2] = pack_f16x2_plain(sacc[2*j+1][0], sacc[2*j+1][1]);
                ap[3] = pack_f16x2_plain(sacc[2*j+1][2], sacc[2*j+1][3]);
                #pragma unroll
                for (int ng = 0; ng < 4; ng++) {
                    uint32_t vf[4];
                    ldmatrix_x4(vf,
                        sV + (ng * 16 + b_n_off) * AT_ROW
                           + (j * 16 + b_k_off) * 2);
                    mma_f16(oacc[2*ng],   ap, vf[0], vf[1]);
                    mma_f16(oacc[2*ng+1], ap, vf[2], vf[3]);
                }
            }

            __syncthreads();
            if (t + 2 < T) {
                issue_stage(t + 2, cur);
                cp_commit();
            } else if (t + 1 < T) {
                cp_commit();
            }
            cur ^= 1;
        }

        // ---- epilogue: quad-reduce rowsums, normalize, store fp16 ----
        sum_lo += __shfl_xor_sync(0xFFFFFFFFu, sum_lo, 1);
        sum_lo += __shfl_xor_sync(0xFFFFFFFFu, sum_lo, 2);
        sum_hi += __shfl_xor_sync(0xFFFFFFFFu, sum_hi, 1);
        sum_hi += __shfl_xor_sync(0xFFFFFFFFu, sum_hi, 2);
        const float inv_lo = 1.0f / sum_lo;
        const float inv_hi = 1.0f / sum_hi;

        const int row_lo = q0 + wm + (lane >> 2);
        #pragma unroll
        for (int nt = 0; nt < 8; nt++) {
            const int d = nt * 8 + (lane & 3) * 2;
            const size_t off0 = (size_t)(b * Sc + row_lo) * Ec + h * Dc + d;
            const size_t off1 = off0 + (size_t)8 * Ec;
            *(uint32_t*)(Yp + off0) =
                pack_f16x2_plain(oacc[nt][0] * inv_lo, oacc[nt][1] * inv_lo);
            *(uint32_t*)(Yp + off1) =
                pack_f16x2_plain(oacc[nt][2] * inv_hi, oacc[nt][3] * inv_hi);
        }
    }
}

// ---------------------------------------------------------------------------
extern "C" void kernel_launch(void* const* d_in, const int* in_sizes, int n_in,
                              void* d_out, int out_size) {
    const float* x      = (const float*)d_in[0];
    const float* W_attn = (const float*)d_in[1];
    const float* b_attn = (const float*)d_in[2];
    const float* W_proj = (const float*)d_in[3];
    const float* b_proj = (const float*)d_in[4];
    float* out = (float*)d_out;

    __half *Xp, *Bp, *Bp2, *Yp, *Qp, *Kp, *Vtp;
    cudaGetSymbolAddress((void**)&Xp, g_Xp);
    cudaGetSymbolAddress((void**)&Bp, g_Bp);
    cudaGetSymbolAddress((void**)&Bp2, g_Bp2);
    cudaGetSymbolAddress((void**)&Yp, g_Yp);
    cudaGetSymbolAddress((void**)&Qp, g_Qp);
    cudaGetSymbolAddress((void**)&Kp, g_Kp);
    cudaGetSymbolAddress((void**)&Vtp, g_Vtp);

    cudaFuncSetAttribute(gemm_mma_kernel<0>,
                         cudaFuncAttributeMaxDynamicSharedMemorySize, GEMM_SMEM);
    cudaFuncSetAttribute(gemm_mma_kernel<1>,
                         cudaFuncAttributeMaxDynamicSharedMemorySize, GEMM_SMEM);
    cudaFuncSetAttribute(attn_mma_kernel,
                         cudaFuncAttributeMaxDynamicSharedMemorySize,
                         ATT_SMEM_BYTES);

    // 1) fused prep
    {
        prep_kernel<<<NB_CVT + NB_TA + NB_TP, 256>>>(x, W_attn, W_proj,
                                                     Xp, Bp, Bp2);
    }
    // 2) QKV GEMM (3-stage), fused epilogue -> attention operands
    {
        dim3 grid(3 * Ec / GBN, MROWS / GBM);
        gemm_mma_kernel<1><<<grid, 256, GEMM_SMEM>>>(Xp, Bp, b_attn,
                                                     nullptr, 3 * Ec, Ec,
                                                     Qp, Kp, Vtp);
    }
    // 3) attention (paired q-tiles, balanced single wave) -> fp16 Yp
    {
        dim3 grid(Sc / 128, BH);  // (16, 32)
        attn_mma_kernel<<<grid, 128, ATT_SMEM_BYTES>>>(Qp, Kp, Vtp, Yp);
    }
    // 4) Proj GEMM (3-stage) -> fp32 out
    {
        dim3 grid(Ec / GBN, MROWS / GBM);
        gemm_mma_kernel<0><<<grid, 256, GEMM_SMEM>>>(Yp, Bp2, b_proj,
                                                     out, Ec, Ec,
                                                     nullptr, nullptr, nullptr);
    }
}

// round 15
// speedup vs baseline: 1.3458x; 1.0574x over previous
#include <cuda_runtime.h>
#include <cuda_fp16.h>
#include <cstdint>
#include <math.h>

// Problem constants
constexpr int Bc = 2, Sc = 2048, Ec = 1024, Hc = 16, Dc = 64;
constexpr int MROWS = Bc * Sc;  // 4096
constexpr int BH = Bc * Hc;     // 32

// ---------------------------------------------------------------------------
// Scratch (device globals: allocation-free). All plain fp16.
// ---------------------------------------------------------------------------
__device__ __half g_Xp[(size_t)MROWS * Ec];    // x plain fp16 (QKV A)
__device__ __half g_Bp[(size_t)3 * Ec * Ec];   // W_attn^T plain fp16
__device__ __half g_Bp2[(size_t)Ec * Ec];      // W_proj^T plain fp16
__device__ __half g_Yp[(size_t)MROWS * Ec];    // attention out (proj A)
// Attention operands: Q (pre-scaled 1/8), K, V transposed — all plain fp16
__device__ __half g_Qp[(size_t)BH * Sc * Dc];
__device__ __half g_Kp[(size_t)BH * Sc * Dc];
__device__ __half g_Vtp[(size_t)BH * Dc * Sc];

// ---------------------------------------------------------------------------
// PTX helpers (sm_80-class base features — safe under compute_103)
// ---------------------------------------------------------------------------
__device__ __forceinline__ uint32_t smem_to_u32(const void* smem_ptr) {
    uint32_t addr;
    asm("{ .reg .u64 tmp; cvta.to.shared.u64 tmp, %1; cvt.u32.u64 %0, tmp; }"
        : "=r"(addr) : "l"(smem_ptr));
    return addr;
}

__device__ __forceinline__ void cp_async16(uint32_t smem_addr, const void* gptr) {
    asm volatile("cp.async.cg.shared.global [%0], [%1], 16;\n"
                 :: "r"(smem_addr), "l"(gptr));
}
__device__ __forceinline__ void cp_commit() {
    asm volatile("cp.async.commit_group;\n" ::: "memory");
}
template <int N>
__device__ __forceinline__ void cp_wait_group() {
    asm volatile("cp.async.wait_group %0;\n" :: "n"(N) : "memory");
}

__device__ __forceinline__ void ldmatrix_x4(uint32_t* r, uint32_t addr) {
    asm volatile("ldmatrix.sync.aligned.m8n8.x4.shared.b16 {%0,%1,%2,%3}, [%4];"
                 : "=r"(r[0]), "=r"(r[1]), "=r"(r[2]), "=r"(r[3]) : "r"(addr));
}

__device__ __forceinline__ void mma_f16(float* c, const uint32_t* a,
                                        uint32_t b0, uint32_t b1) {
    asm volatile(
        "mma.sync.aligned.m16n8k16.row.col.f32.f16.f16.f32 "
        "{%0,%1,%2,%3}, {%4,%5,%6,%7}, {%8,%9}, {%0,%1,%2,%3};"
        : "+f"(c[0]), "+f"(c[1]), "+f"(c[2]), "+f"(c[3])
        : "r"(a[0]), "r"(a[1]), "r"(a[2]), "r"(a[3]), "r"(b0), "r"(b1));
}

__device__ __forceinline__ uint32_t pack_f16x2_plain(float p0, float p1) {
    __half2 h2 = __floats2half2_rn(p0, p1);   // p0 -> low half
    return *reinterpret_cast<uint32_t*>(&h2);
}

// ---------------------------------------------------------------------------
// Fused prep kernel (convert x + both W transposes in one launch)
// ---------------------------------------------------------------------------
constexpr int NB_CVT = (MROWS * Ec) / 256;          // 16384
constexpr int NB_TA  = (3 * Ec / 32) * (Ec / 32);   // 3072
constexpr int NB_TP  = (Ec / 32) * (Ec / 32);       // 1024

__global__ __launch_bounds__(256)
void prep_kernel(const float* __restrict__ x,
                 const float* __restrict__ W_attn,
                 const float* __restrict__ W_proj,
                 __half* __restrict__ Xp,
                 __half* __restrict__ Bp,
                 __half* __restrict__ Bp2) {
    const int bid = blockIdx.x;
    const int t   = threadIdx.x;
    if (bid < NB_CVT) {
        const int i = bid * 256 + t;
        Xp[i] = __float2half_rn(x[i]);
        return;
    }
    __shared__ float ts[32][33];
    const float* W;
    __half* Bt;
    int K = Ec, N, bx, by;
    if (bid < NB_CVT + NB_TA) {
        const int idx = bid - NB_CVT;
        W = W_attn; Bt = Bp; N = 3 * Ec;
        bx = idx % (3 * Ec / 32); by = idx / (3 * Ec / 32);
    } else {
        const int idx = bid - NB_CVT - NB_TA;
        W = W_proj; Bt = Bp2; N = Ec;
        bx = idx % (Ec / 32); by = idx / (Ec / 32);
    }
    const int k0 = by * 32;
    const int n0 = bx * 32;
    const int tx = t & 31;
    const int ty = t >> 5;
    #pragma unroll
    for (int i = 0; i < 4; i++)
        ts[ty + i * 8][tx] = W[(size_t)(k0 + ty + i * 8) * N + n0 + tx];
    __syncthreads();
    #pragma unroll
    for (int i = 0; i < 4; i++) {
        float v = ts[tx][ty + i * 8];
        Bt[(size_t)(n0 + ty + i * 8) * K + k0 + tx] = __float2half_rn(v);
    }
}

// ---------------------------------------------------------------------------
// HMMA plain-fp16 GEMM (fp32 accumulate), BK=64, 2-stage cp.async.
// 128-THREAD / 128x64-TILE config: 4 warps, warp tile 32x64 (wn=0), smem
// 55.3KB -> 4 CTAs/SM = 4 warps/SMSP (vs 2 before). Attention at 4 warps/SMSP
// reaches ~90% of the mma.sync rt=16 ceiling; this brings the GEMMs there.
// Per-element K summation order unchanged -> bitwise-identical output.
// MODE 0: C=fp32 (+bias). MODE 1: QKV-fused epilogue (fp16 Q/K/Vt).
// ---------------------------------------------------------------------------
constexpr int GBM = 128, GBN = 64, GBK = 64;
constexpr int G_PITCH   = 144;
constexpr int G_ATILE_B = 128 * G_PITCH;            // 18432
constexpr int G_BTILE_B = 64 * G_PITCH;             // 9216
constexpr int G_STAGE_B = G_ATILE_B + G_BTILE_B;    // 27648
constexpr int GEMM_SMEM = 2 * G_STAGE_B;            // 55296 (>= V-epi 33280)

template <int MODE>
__global__ __launch_bounds__(128, 4)
void gemm_mma_kernel(const __half* __restrict__ Ap,
                     const __half* __restrict__ Bp,
                     const float* __restrict__ bias,
                     float* __restrict__ C,
                     int N, int K,
                     __half* __restrict__ Qp,
                     __half* __restrict__ Kp,
                     __half* __restrict__ Vtp) {
    extern __shared__ __align__(128) char gsm[];
    const uint32_t smb = smem_to_u32(gsm);

    const int tid  = threadIdx.x;
    const int wid  = tid >> 5;
    const int lane = tid & 31;
    const int m0 = blockIdx.y * GBM;
    const int n0 = blockIdx.x * GBN;
    const int wm = wid * 32;           // 4 warps x 32 rows

    const int kiters = K / GBK;  // 16

    float acc[2][8][4] = {};

    const int a_row_off = lane & 15;
    const int a_k_off   = (lane >> 4) * 8;
    const int b_n_off   = ((lane >> 4) & 1) * 8 + (lane & 7);
    const int b_k_off   = ((lane >> 3) & 1) * 8;

    auto issue_load = [&](int it, int stage) {
        const int kc = it * GBK;
        const uint32_t sb = smb + stage * G_STAGE_B;
        // A: 128 rows x 8 x16B = 1024 chunks, 8 per thread
        #pragma unroll
        for (int c = 0; c < 8; c++) {
            const int chunk = tid + c * 128;
            const int row = chunk >> 3;
            const int c16 = chunk & 7;
            cp_async16(sb + row * G_PITCH + c16 * 16,
                       Ap + (size_t)(m0 + row) * K + kc + c16 * 8);
        }
        // B: 64 rows x 8 = 512 chunks, 4 per thread
        #pragma unroll
        for (int c = 0; c < 4; c++) {
            const int chunk = tid + c * 128;
            const int row = chunk >> 3;
            const int c16 = chunk & 7;
            cp_async16(sb + G_ATILE_B + row * G_PITCH + c16 * 16,
                       Bp + (size_t)(n0 + row) * K + kc + c16 * 8);
        }
    };

    issue_load(0, 0);
    cp_commit();

    int cur = 0;
    for (int it = 0; it < kiters; it++) {
        if (it + 1 < kiters) {
            issue_load(it + 1, cur ^ 1);
            cp_commit();
            cp_wait_group<1>();
        } else {
            cp_wait_group<0>();
        }
        __syncthreads();

        const uint32_t sb = smb + cur * G_STAGE_B;
        #pragma unroll
        for (int ks = 0; ks < 4; ks++) {
            const int k0 = ks * 16;
            uint32_t af[2][4], bf[4][4];
            #pragma unroll
            for (int mt = 0; mt < 2; mt++) {
                ldmatrix_x4(af[mt], sb
                            + (wm + mt * 16 + a_row_off) * G_PITCH
                            + (k0 + a_k_off) * 2);
            }
            #pragma unroll
            for (int ng = 0; ng < 4; ng++) {
                ldmatrix_x4(bf[ng], sb + G_ATILE_B
                            + (ng * 16 + b_n_off) * G_PITCH
                            + (k0 + b_k_off) * 2);
            }
            #pragma unroll
            for (int mt = 0; mt < 2; mt++) {
                #pragma unroll
                for (int ng = 0; ng < 4; ng++) {
                    mma_f16(acc[mt][2*ng],   af[mt], bf[ng][0], bf[ng][1]);
                    mma_f16(acc[mt][2*ng+1], af[mt], bf[ng][2], bf[ng][3]);
                }
            }
        }
        __syncthreads();
        cur ^= 1;
    }

    if (MODE == 0) {
        #pragma unroll
        for (int mt = 0; mt < 2; mt++) {
            const int row = m0 + wm + mt * 16 + (lane >> 2);
            #pragma unroll
            for (int nt = 0; nt < 8; nt++) {
                const int col = n0 + nt * 8 + (lane & 3) * 2;
                const float b0 = bias[col], b1 = bias[col + 1];
                float2 o0 = {acc[mt][nt][0] + b0, acc[mt][nt][1] + b1};
                float2 o1 = {acc[mt][nt][2] + b0, acc[mt][nt][3] + b1};
                *(float2*)(C + (size_t)row * N + col) = o0;
                *(float2*)(C + (size_t)(row + 8) * N + col) = o1;
            }
        }
    } else {
        const int sec = n0 >> 10;        // 0=Q, 1=K, 2=V (64 | 1024 -> uniform)
        const int b   = m0 >> 11;
        const int s0t = m0 & 2047;
        if (sec < 2) {
            __half* Tp = (sec == 0) ? Qp : Kp;
            const float scale = (sec == 0) ? 0.125f : 1.0f;
            #pragma unroll
            for (int mt = 0; mt < 2; mt++) {
                const int s = s0t + wm + mt * 16 + (lane >> 2);
                #pragma unroll
                for (int nt = 0; nt < 8; nt++) {
                    const int col = n0 + nt * 8 + (lane & 3) * 2;
                    const int e = col & 1023;
                    const int h = e >> 6, d = e & 63;
                    const size_t rowb = (size_t)(b * Hc + h) * Sc;
                    const float bb0 = bias[col], bb1 = bias[col + 1];
                    *(uint32_t*)(Tp + (rowb + s) * Dc + d) =
                        pack_f16x2_plain((acc[mt][nt][0] + bb0) * scale,
                                         (acc[mt][nt][1] + bb1) * scale);
                    *(uint32_t*)(Tp + (rowb + s + 8) * Dc + d) =
                        pack_f16x2_plain((acc[mt][nt][2] + bb0) * scale,
                                         (acc[mt][nt][3] + bb1) * scale);
                }
            }
        } else {
            // V: fp32+bias staged in smem [128][65], transposed fp16 writes
            float* smT = (float*)gsm;
            #pragma unroll
            for (int mt = 0; mt < 2; mt++) {
                const int r = wm + mt * 16 + (lane >> 2);
                #pragma unroll
                for (int nt = 0; nt < 8; nt++) {
                    const int c = nt * 8 + (lane & 3) * 2;
                    const int col = n0 + c;
                    const float bb0 = bias[col], bb1 = bias[col + 1];
                    smT[r * 65 + c]           = acc[mt][nt][0] + bb0;
                    smT[r * 65 + c + 1]       = acc[mt][nt][1] + bb1;
                    smT[(r + 8) * 65 + c]     = acc[mt][nt][2] + bb0;
                    smT[(r + 8) * 65 + c + 1] = acc[mt][nt][3] + bb1;
                }
            }
            __syncthreads();
            const int c  = tid & 63;            // d within tile (64 cols)
            const int sh = (tid >> 6) * 64;     // s-half (0 or 64)
            const int e  = (n0 + c) & 1023;
            const int h  = e >> 6, d = e & 63;
            const size_t vbase = ((size_t)(b * Hc + h) * Dc + d) * Sc + s0t + sh;
            #pragma unroll
            for (int s = 0; s < 64; s += 2) {
                *(uint32_t*)(Vtp + vbase + s) =
                    pack_f16x2_plain(smT[(sh + s) * 65 + c],
                                     smT[(sh + s + 1) * 65 + c]);
            }
        }
    }
}

// ---------------------------------------------------------------------------
// Tensor-core causal flash attention, all plain fp16 (fp32 accumulate).
// Q-TILE PAIRING: CTA bx processes q-tiles {2*Gx-1-bx, bx}; every CTA does
// exactly 2*Gx+1 ktiles -> one perfectly balanced wave (512 CTAs, 4/SM).
// (Round-12 form; at ~90% of the mma.sync issue ceiling.)
// ---------------------------------------------------------------------------
constexpr int AT_ROW = 144;
constexpr int AT_TILE_B = 64 * AT_ROW;         // 9216
constexpr int ATT_SMEM_BYTES = 5 * AT_TILE_B;  // 46080

__global__ __launch_bounds__(128, 4)
void attn_mma_kernel(const __half* __restrict__ Qp,
                     const __half* __restrict__ Kp,
                     const __half* __restrict__ Vtp,
                     __half* __restrict__ Yp) {
    extern __shared__ __half smf[];
    const uint32_t smb = smem_to_u32(smf);

    const int bh = blockIdx.y;
    const int b  = bh >> 4;
    const int h  = bh & 15;
    const int tid  = threadIdx.x;
    const int wid  = tid >> 5;
    const int lane = tid & 31;
    const int wm   = wid * 16;

    const size_t bhQK = (size_t)bh * Sc * Dc;
    const size_t bhVT = (size_t)bh * Dc * Sc;

    const uint32_t sQ_a = smb;
    auto stage_addr = [&](int buf, int t) -> uint32_t {
        return smb + (1 + buf * 2 + t) * AT_TILE_B;
    };

    auto load_qk_tile = [&](uint32_t sa, const __half* src, int s0) {
        #pragma unroll
        for (int i = 0; i < 4; i++) {
            const int idx = tid + i * 128;
            const int row = idx >> 3;
            const int c16 = idx & 7;
            cp_async16(sa + row * AT_ROW + c16 * 16,
                       src + bhQK + (size_t)(s0 + row) * Dc + c16 * 8);
        }
    };
    auto load_vt_tile = [&](uint32_t sa, const __half* src, int kb) {
        #pragma unroll
        for (int i = 0; i < 4; i++) {
            const int idx = tid + i * 128;
            const int row = idx >> 3;
            const int c16 = idx & 7;
            cp_async16(sa + row * AT_ROW + c16 * 16,
                       src + bhVT + (size_t)row * Sc + kb + c16 * 8);
        }
    };
    auto issue_stage = [&](int t, int buf) {
        const int kb = t * 64;
        load_qk_tile(stage_addr(buf, 0), Kp, kb);
        load_vt_tile(stage_addr(buf, 1), Vtp, kb);
    };

    const int a_row_off = lane & 15;
    const int a_k_off   = (lane >> 4) * 8;
    const int b_n_off   = ((lane >> 4) & 1) * 8 + (lane & 7);
    const int b_k_off   = ((lane >> 3) & 1) * 8;

    #pragma unroll 1
    for (int qi = 0; qi < 2; qi++) {
        const int qt = (qi == 0) ? (2 * gridDim.x - 1 - blockIdx.x)
                                 : blockIdx.x;
        const int q0 = qt * 64;
        const int T = qt + 1;

        load_qk_tile(sQ_a, Qp, q0);
        issue_stage(0, 0);
        cp_commit();
        if (T > 1) issue_stage(1, 1);
        cp_commit();

        uint32_t qf[4][4];
        float oacc[8][4] = {};
        float sum_lo = 0.f, sum_hi = 0.f;

        int cur = 0;
        for (int t = 0; t < T; t++) {
            if (t == 0) {
                cp_wait_group<1>();
                __syncthreads();
                #pragma unroll
                for (int ks = 0; ks < 4; ks++) {
                    ldmatrix_x4(qf[ks],
                        sQ_a + (wm + a_row_off) * AT_ROW
                             + (ks * 16 + a_k_off) * 2);
                }
            } else if (t + 1 < T) {
                cp_wait_group<1>();
                __syncthreads();
            } else {
                cp_wait_group<0>();
                __syncthreads();
            }

            const uint32_t sK = stage_addr(cur, 0);
            const uint32_t sV = stage_addr(cur, 1);

            // ---- QK^T ----
            float sacc[8][4] = {};
            #pragma unroll
            for (int ks = 0; ks < 4; ks++) {
                uint32_t kf[4][4];
                #pragma unroll
                for (int ng = 0; ng < 4; ng++) {
                    ldmatrix_x4(kf[ng],
                        sK + (ng * 16 + b_n_off) * AT_ROW
                           + (ks * 16 + b_k_off) * 2);
                }
                #pragma unroll
                for (int ng = 0; ng < 4; ng++) {
                    mma_f16(sacc[2*ng],   qf[ks], kf[ng][0], kf[ng][1]);
                    mma_f16(sacc[2*ng+1], qf[ks], kf[ng][2], kf[ng][3]);
                }
            }

            // ---- causal mask (diagonal tile only) + exp + rowsum ----
            if (t == T - 1) {
                const int rlo = wm + (lane >> 2);
                #pragma unroll
                for (int nt = 0; nt < 8; nt++) {
                    const int c = nt * 8 + (lane & 3) * 2;
                    if (c > rlo)         sacc[nt][0] = -1e30f;
                    if (c + 1 > rlo)     sacc[nt][1] = -1e30f;
                    if (c > rlo + 8)     sacc[nt][2] = -1e30f;
                    if (c + 1 > rlo + 8) sacc[nt][3] = -1e30f;
                }
            }
            #pragma unroll
            for (int nt = 0; nt < 8; nt++) {
                sacc[nt][0] = __expf(sacc[nt][0]);
                sacc[nt][1] = __expf(sacc[nt][1]);
                sacc[nt][2] = __expf(sacc[nt][2]);
                sacc[nt][3] = __expf(sacc[nt][3]);
                sum_lo += sacc[nt][0] + sacc[nt][1];
                sum_hi += sacc[nt][2] + sacc[nt][3];
            }

            // ---- P·V ----
            #pragma unroll
            for (int j = 0; j < 4; j++) {
                uint32_t ap[4];
                ap[0] = pack_f16x2_plain(sacc[2*j][0],   sacc[2*j][1]);
                ap[1] = pack_f16x2_plain(sacc[2*j][2],   sacc[2*j][3]);
                ap[2] = pack_f16x2_plain(sacc[2*j+1][0], sacc[2*j+1][1]);
                ap[3] = pack_f16x2_plain(sacc[2*j+1][2], sacc[2*j+1][3]);
                #pragma unroll
                for (int ng = 0; ng < 4; ng++) {
                    uint32_t vf[4];
                    ldmatrix_x4(vf,
                        sV + (ng * 16 + b_n_off) * AT_ROW
                           + (j * 16 + b_k_off) * 2);
                    mma_f16(oacc[2*ng],   ap, vf[0], vf[1]);
                    mma_f16(oacc[2*ng+1], ap, vf[2], vf[3]);
                }
            }

            __syncthreads();
            if (t + 2 < T) {
                issue_stage(t + 2, cur);
                cp_commit();
            } else if (t + 1 < T) {
                cp_commit();
            }
            cur ^= 1;
        }

        // ---- epilogue: quad-reduce rowsums, normalize, store fp16 ----
        sum_lo += __shfl_xor_sync(0xFFFFFFFFu, sum_lo, 1);
        sum_lo += __shfl_xor_sync(0xFFFFFFFFu, sum_lo, 2);
        sum_hi += __shfl_xor_sync(0xFFFFFFFFu, sum_hi, 1);
        sum_hi += __shfl_xor_sync(0xFFFFFFFFu, sum_hi, 2);
        const float inv_lo = 1.0f / sum_lo;
        const float inv_hi = 1.0f / sum_hi;

        const int row_lo = q0 + wm + (lane >> 2);
        #pragma unroll
        for (int nt = 0; nt < 8; nt++) {
            const int d = nt * 8 + (lane & 3) * 2;
            const size_t off0 = (size_t)(b * Sc + row_lo) * Ec + h * Dc + d;
            const size_t off1 = off0 + (size_t)8 * Ec;
            *(uint32_t*)(Yp + off0) =
                pack_f16x2_plain(oacc[nt][0] * inv_lo, oacc[nt][1] * inv_lo);
            *(uint32_t*)(Yp + off1) =
                pack_f16x2_plain(oacc[nt][2] * inv_hi, oacc[nt][3] * inv_hi);
        }
    }
}

// ---------------------------------------------------------------------------
extern "C" void kernel_launch(void* const* d_in, const int* in_sizes, int n_in,
                              void* d_out, int out_size) {
    const float* x      = (const float*)d_in[0];
    const float* W_attn = (const float*)d_in[1];
    const float* b_attn = (const float*)d_in[2];
    const float* W_proj = (const float*)d_in[3];
    const float* b_proj = (const float*)d_in[4];
    float* out = (float*)d_out;

    __half *Xp, *Bp, *Bp2, *Yp, *Qp, *Kp, *Vtp;
    cudaGetSymbolAddress((void**)&Xp, g_Xp);
    cudaGetSymbolAddress((void**)&Bp, g_Bp);
    cudaGetSymbolAddress((void**)&Bp2, g_Bp2);
    cudaGetSymbolAddress((void**)&Yp, g_Yp);
    cudaGetSymbolAddress((void**)&Qp, g_Qp);
    cudaGetSymbolAddress((void**)&Kp, g_Kp);
    cudaGetSymbolAddress((void**)&Vtp, g_Vtp);

    cudaFuncSetAttribute(gemm_mma_kernel<0>,
                         cudaFuncAttributeMaxDynamicSharedMemorySize, GEMM_SMEM);
    cudaFuncSetAttribute(gemm_mma_kernel<1>,
                         cudaFuncAttributeMaxDynamicSharedMemorySize, GEMM_SMEM);
    cudaFuncSetAttribute(attn_mma_kernel,
                         cudaFuncAttributeMaxDynamicSharedMemorySize,
                         ATT_SMEM_BYTES);

    // 1) fused prep
    {
        prep_kernel<<<NB_CVT + NB_TA + NB_TP, 256>>>(x, W_attn, W_proj,
                                                     Xp, Bp, Bp2);
    }
    // 2) QKV GEMM (128x64 tiles, 4 CTAs/SM), fused epilogue -> attn operands
    {
        dim3 grid(3 * Ec / GBN, MROWS / GBM);  // (48, 32)
        gemm_mma_kernel<1><<<grid, 128, GEMM_SMEM>>>(Xp, Bp, b_attn,
                                                     nullptr, 3 * Ec, Ec,
                                                     Qp, Kp, Vtp);
    }
    // 3) attention (paired q-tiles, balanced single wave) -> fp16 Yp
    {
        dim3 grid(Sc / 128, BH);  // (16, 32)
        attn_mma_kernel<<<grid, 128, ATT_SMEM_BYTES>>>(Qp, Kp, Vtp, Yp);
    }
    // 4) Proj GEMM (128x64 tiles; 512 CTAs = one exact 4/SM wave) -> fp32 out
    {
        dim3 grid(Ec / GBN, MROWS / GBM);  // (16, 32)
        gemm_mma_kernel<0><<<grid, 128, GEMM_SMEM>>>(Yp, Bp2, b_proj,
                                                     out, Ec, Ec,
                                                     nullptr, nullptr, nullptr);
    }
}

// round 16
// speedup vs baseline: 1.3898x; 1.0327x over previous
#include <cuda_runtime.h>
#include <cuda_fp16.h>
#include <cstdint>
#include <math.h>

// Problem constants
constexpr int Bc = 2, Sc = 2048, Ec = 1024, Hc = 16, Dc = 64;
constexpr int MROWS = Bc * Sc;  // 4096
constexpr int BH = Bc * Hc;     // 32

// ---------------------------------------------------------------------------
// Scratch (device globals: allocation-free). All plain fp16.
// ---------------------------------------------------------------------------
__device__ __half g_Xp[(size_t)MROWS * Ec];    // x plain fp16 (QKV A)
__device__ __half g_Bp[(size_t)3 * Ec * Ec];   // W_attn^T plain fp16
__device__ __half g_Bp2[(size_t)Ec * Ec];      // W_proj^T plain fp16
__device__ __half g_Yp[(size_t)MROWS * Ec];    // attention out (proj A)
// Attention operands: Q (pre-scaled 0.125*log2e), K, V^T — all plain fp16
__device__ __half g_Qp[(size_t)BH * Sc * Dc];
__device__ __half g_Kp[(size_t)BH * Sc * Dc];
__device__ __half g_Vtp[(size_t)BH * Dc * Sc];

// ---------------------------------------------------------------------------
// PTX helpers (sm_80-class base features — safe under compute_103)
// ---------------------------------------------------------------------------
__device__ __forceinline__ uint32_t smem_to_u32(const void* smem_ptr) {
    uint32_t addr;
    asm("{ .reg .u64 tmp; cvta.to.shared.u64 tmp, %1; cvt.u32.u64 %0, tmp; }"
        : "=r"(addr) : "l"(smem_ptr));
    return addr;
}

__device__ __forceinline__ void cp_async16(uint32_t smem_addr, const void* gptr) {
    asm volatile("cp.async.cg.shared.global [%0], [%1], 16;\n"
                 :: "r"(smem_addr), "l"(gptr));
}
__device__ __forceinline__ void cp_commit() {
    asm volatile("cp.async.commit_group;\n" ::: "memory");
}
template <int N>
__device__ __forceinline__ void cp_wait_group() {
    asm volatile("cp.async.wait_group %0;\n" :: "n"(N) : "memory");
}

__device__ __forceinline__ void ldmatrix_x4(uint32_t* r, uint32_t addr) {
    asm volatile("ldmatrix.sync.aligned.m8n8.x4.shared.b16 {%0,%1,%2,%3}, [%4];"
                 : "=r"(r[0]), "=r"(r[1]), "=r"(r[2]), "=r"(r[3]) : "r"(addr));
}

__device__ __forceinline__ void mma_f16(float* c, const uint32_t* a,
                                        uint32_t b0, uint32_t b1) {
    asm volatile(
        "mma.sync.aligned.m16n8k16.row.col.f32.f16.f16.f32 "
        "{%0,%1,%2,%3}, {%4,%5,%6,%7}, {%8,%9}, {%0,%1,%2,%3};"
        : "+f"(c[0]), "+f"(c[1]), "+f"(c[2]), "+f"(c[3])
        : "r"(a[0]), "r"(a[1]), "r"(a[2]), "r"(a[3]), "r"(b0), "r"(b1));
}

__device__ __forceinline__ uint32_t pack_f16x2_plain(float p0, float p1) {
    __half2 h2 = __floats2half2_rn(p0, p1);   // p0 -> low half
    return *reinterpret_cast<uint32_t*>(&h2);
}

// Raw exp2 (no pre-multiply; log2e folded into Q pre-scale)
__device__ __forceinline__ float ex2f(float x) {
    float r;
    asm("ex2.approx.f32 %0, %1;" : "=f"(r) : "f"(x));
    return r;
}

// ---------------------------------------------------------------------------
// Fused prep kernel (vectorized x convert + both W transposes, one launch)
// ---------------------------------------------------------------------------
constexpr int NB_CVT = (MROWS * Ec) / (256 * 4);    // 4096 (4 elems/thread)
constexpr int NB_TA  = (3 * Ec / 32) * (Ec / 32);   // 3072
constexpr int NB_TP  = (Ec / 32) * (Ec / 32);       // 1024

__global__ __launch_bounds__(256)
void prep_kernel(const float* __restrict__ x,
                 const float* __restrict__ W_attn,
                 const float* __restrict__ W_proj,
                 __half* __restrict__ Xp,
                 __half* __restrict__ Bp,
                 __half* __restrict__ Bp2) {
    const int bid = blockIdx.x;
    const int t   = threadIdx.x;
    if (bid < NB_CVT) {
        const int i = (bid * 256 + t) * 4;
        float4 v = *(const float4*)(x + i);
        uint32_t lo = pack_f16x2_plain(v.x, v.y);
        uint32_t hi = pack_f16x2_plain(v.z, v.w);
        *(uint2*)(Xp + i) = make_uint2(lo, hi);
        return;
    }
    __shared__ float ts[32][33];
    const float* W;
    __half* Bt;
    int K = Ec, N, bx, by;
    if (bid < NB_CVT + NB_TA) {
        const int idx = bid - NB_CVT;
        W = W_attn; Bt = Bp; N = 3 * Ec;
        bx = idx % (3 * Ec / 32); by = idx / (3 * Ec / 32);
    } else {
        const int idx = bid - NB_CVT - NB_TA;
        W = W_proj; Bt = Bp2; N = Ec;
        bx = idx % (Ec / 32); by = idx / (Ec / 32);
    }
    const int k0 = by * 32;
    const int n0 = bx * 32;
    const int tx = t & 31;
    const int ty = t >> 5;
    #pragma unroll
    for (int i = 0; i < 4; i++)
        ts[ty + i * 8][tx] = W[(size_t)(k0 + ty + i * 8) * N + n0 + tx];
    __syncthreads();
    #pragma unroll
    for (int i = 0; i < 4; i++) {
        float v = ts[tx][ty + i * 8];
        Bt[(size_t)(n0 + ty + i * 8) * K + k0 + tx] = __float2half_rn(v);
    }
}

// ---------------------------------------------------------------------------
// HMMA plain-fp16 GEMM (fp32 accumulate), BK=64, 2-stage cp.async.
// 128 threads / 128x64 tile (4 warps, warp tile 32x64).
// MODE 0: C=fp32 (+bias). MODE 1: QKV-fused epilogue (fp16 Q/K/Vt);
// Q pre-scale = 0.125 * log2(e) so attention can use raw ex2.
// ---------------------------------------------------------------------------
constexpr int GBM = 128, GBN = 64, GBK = 64;
constexpr int G_PITCH   = 144;
constexpr int G_ATILE_B = 128 * G_PITCH;            // 18432
constexpr int G_BTILE_B = 64 * G_PITCH;             // 9216
constexpr int G_STAGE_B = G_ATILE_B + G_BTILE_B;    // 27648
constexpr int GEMM_SMEM = 2 * G_STAGE_B;            // 55296

__device__ __constant__ float kQScale = 0.125f * 1.44269504088896341f;

template <int MODE>
__global__ __launch_bounds__(128, 4)
void gemm_mma_kernel(const __half* __restrict__ Ap,
                     const __half* __restrict__ Bp,
                     const float* __restrict__ bias,
                     float* __restrict__ C,
                     int N, int K,
                     __half* __restrict__ Qp,
                     __half* __restrict__ Kp,
                     __half* __restrict__ Vtp) {
    extern __shared__ __align__(128) char gsm[];
    const uint32_t smb = smem_to_u32(gsm);

    const int tid  = threadIdx.x;
    const int wid  = tid >> 5;
    const int lane = tid & 31;
    const int m0 = blockIdx.y * GBM;
    const int n0 = blockIdx.x * GBN;
    const int wm = wid * 32;

    const int kiters = K / GBK;  // 16

    float acc[2][8][4] = {};

    const int a_row_off = lane & 15;
    const int a_k_off   = (lane >> 4) * 8;
    const int b_n_off   = ((lane >> 4) & 1) * 8 + (lane & 7);
    const int b_k_off   = ((lane >> 3) & 1) * 8;

    auto issue_load = [&](int it, int stage) {
        const int kc = it * GBK;
        const uint32_t sb = smb + stage * G_STAGE_B;
        #pragma unroll
        for (int c = 0; c < 8; c++) {
            const int chunk = tid + c * 128;
            const int row = chunk >> 3;
            const int c16 = chunk & 7;
            cp_async16(sb + row * G_PITCH + c16 * 16,
                       Ap + (size_t)(m0 + row) * K + kc + c16 * 8);
        }
        #pragma unroll
        for (int c = 0; c < 4; c++) {
            const int chunk = tid + c * 128;
            const int row = chunk >> 3;
            const int c16 = chunk & 7;
            cp_async16(sb + G_ATILE_B + row * G_PITCH + c16 * 16,
                       Bp + (size_t)(n0 + row) * K + kc + c16 * 8);
        }
    };

    issue_load(0, 0);
    cp_commit();

    int cur = 0;
    for (int it = 0; it < kiters; it++) {
        if (it + 1 < kiters) {
            issue_load(it + 1, cur ^ 1);
            cp_commit();
            cp_wait_group<1>();
        } else {
            cp_wait_group<0>();
        }
        __syncthreads();

        const uint32_t sb = smb + cur * G_STAGE_B;
        #pragma unroll
        for (int ks = 0; ks < 4; ks++) {
            const int k0 = ks * 16;
            uint32_t af[2][4], bf[4][4];
            #pragma unroll
            for (int mt = 0; mt < 2; mt++) {
                ldmatrix_x4(af[mt], sb
                            + (wm + mt * 16 + a_row_off) * G_PITCH
                            + (k0 + a_k_off) * 2);
            }
            #pragma unroll
            for (int ng = 0; ng < 4; ng++) {
                ldmatrix_x4(bf[ng], sb + G_ATILE_B
                            + (ng * 16 + b_n_off) * G_PITCH
                            + (k0 + b_k_off) * 2);
            }
            #pragma unroll
            for (int mt = 0; mt < 2; mt++) {
                #pragma unroll
                for (int ng = 0; ng < 4; ng++) {
                    mma_f16(acc[mt][2*ng],   af[mt], bf[ng][0], bf[ng][1]);
                    mma_f16(acc[mt][2*ng+1], af[mt], bf[ng][2], bf[ng][3]);
                }
            }
        }
        __syncthreads();
        cur ^= 1;
    }

    if (MODE == 0) {
        #pragma unroll
        for (int mt = 0; mt < 2; mt++) {
            const int row = m0 + wm + mt * 16 + (lane >> 2);
            #pragma unroll
            for (int nt = 0; nt < 8; nt++) {
                const int col = n0 + nt * 8 + (lane & 3) * 2;
                const float b0 = bias[col], b1 = bias[col + 1];
                float2 o0 = {acc[mt][nt][0] + b0, acc[mt][nt][1] + b1};
                float2 o1 = {acc[mt][nt][2] + b0, acc[mt][nt][3] + b1};
                *(float2*)(C + (size_t)row * N + col) = o0;
                *(float2*)(C + (size_t)(row + 8) * N + col) = o1;
            }
        }
    } else {
        const int sec = n0 >> 10;        // 0=Q, 1=K, 2=V
        const int b   = m0 >> 11;
        const int s0t = m0 & 2047;
        if (sec < 2) {
            __half* Tp = (sec == 0) ? Qp : Kp;
            const float scale = (sec == 0) ? kQScale : 1.0f;
            #pragma unroll
            for (int mt = 0; mt < 2; mt++) {
                const int s = s0t + wm + mt * 16 + (lane >> 2);
                #pragma unroll
                for (int nt = 0; nt < 8; nt++) {
                    const int col = n0 + nt * 8 + (lane & 3) * 2;
                    const int e = col & 1023;
                    const int h = e >> 6, d = e & 63;
                    const size_t rowb = (size_t)(b * Hc + h) * Sc;
                    const float bb0 = bias[col], bb1 = bias[col + 1];
                    *(uint32_t*)(Tp + (rowb + s) * Dc + d) =
                        pack_f16x2_plain((acc[mt][nt][0] + bb0) * scale,
                                         (acc[mt][nt][1] + bb1) * scale);
                    *(uint32_t*)(Tp + (rowb + s + 8) * Dc + d) =
                        pack_f16x2_plain((acc[mt][nt][2] + bb0) * scale,
                                         (acc[mt][nt][3] + bb1) * scale);
                }
            }
        } else {
            // V: fp32+bias staged in smem [128][65], transposed fp16 writes
            float* smT = (float*)gsm;
            #pragma unroll
            for (int mt = 0; mt < 2; mt++) {
                const int r = wm + mt * 16 + (lane >> 2);
                #pragma unroll
                for (int nt = 0; nt < 8; nt++) {
                    const int c = nt * 8 + (lane & 3) * 2;
                    const int col = n0 + c;
                    const float bb0 = bias[col], bb1 = bias[col + 1];
                    smT[r * 65 + c]           = acc[mt][nt][0] + bb0;
                    smT[r * 65 + c + 1]       = acc[mt][nt][1] + bb1;
                    smT[(r + 8) * 65 + c]     = acc[mt][nt][2] + bb0;
                    smT[(r + 8) * 65 + c + 1] = acc[mt][nt][3] + bb1;
                }
            }
            __syncthreads();
            const int c  = tid & 63;
            const int sh = (tid >> 6) * 64;
            const int e  = (n0 + c) & 1023;
            const int h  = e >> 6, d = e & 63;
            const size_t vbase = ((size_t)(b * Hc + h) * Dc + d) * Sc + s0t + sh;
            #pragma unroll
            for (int s = 0; s < 64; s += 2) {
                *(uint32_t*)(Vtp + vbase + s) =
                    pack_f16x2_plain(smT[(sh + s) * 65 + c],
                                     smT[(sh + s + 1) * 65 + c]);
            }
        }
    }
}

// ---------------------------------------------------------------------------
// Tensor-core causal flash attention, all plain fp16 (fp32 accumulate).
// Q pre-scaled by 0.125*log2e -> softmax uses raw ex2.approx (no FMUL).
// Q-TILE PAIRING: one perfectly balanced wave (512 CTAs).
// ---------------------------------------------------------------------------
constexpr int AT_ROW = 144;
constexpr int AT_TILE_B = 64 * AT_ROW;         // 9216
constexpr int ATT_SMEM_BYTES = 5 * AT_TILE_B;  // 46080

__global__ __launch_bounds__(128, 4)
void attn_mma_kernel(const __half* __restrict__ Qp,
                     const __half* __restrict__ Kp,
                     const __half* __restrict__ Vtp,
                     __half* __restrict__ Yp) {
    extern __shared__ __half smf[];
    const uint32_t smb = smem_to_u32(smf);

    const int bh = blockIdx.y;
    const int b  = bh >> 4;
    const int h  = bh & 15;
    const int tid  = threadIdx.x;
    const int wid  = tid >> 5;
    const int lane = tid & 31;
    const int wm   = wid * 16;

    const size_t bhQK = (size_t)bh * Sc * Dc;
    const size_t bhVT = (size_t)bh * Dc * Sc;

    const uint32_t sQ_a = smb;
    auto stage_addr = [&](int buf, int t) -> uint32_t {
        return smb + (1 + buf * 2 + t) * AT_TILE_B;
    };

    auto load_qk_tile = [&](uint32_t sa, const __half* src, int s0) {
        #pragma unroll
        for (int i = 0; i < 4; i++) {
            const int idx = tid + i * 128;
            const int row = idx >> 3;
            const int c16 = idx & 7;
            cp_async16(sa + row * AT_ROW + c16 * 16,
                       src + bhQK + (size_t)(s0 + row) * Dc + c16 * 8);
        }
    };
    auto load_vt_tile = [&](uint32_t sa, const __half* src, int kb) {
        #pragma unroll
        for (int i = 0; i < 4; i++) {
            const int idx = tid + i * 128;
            const int row = idx >> 3;
            const int c16 = idx & 7;
            cp_async16(sa + row * AT_ROW + c16 * 16,
                       src + bhVT + (size_t)row * Sc + kb + c16 * 8);
        }
    };
    auto issue_stage = [&](int t, int buf) {
        const int kb = t * 64;
        load_qk_tile(stage_addr(buf, 0), Kp, kb);
        load_vt_tile(stage_addr(buf, 1), Vtp, kb);
    };

    const int a_row_off = lane & 15;
    const int a_k_off   = (lane >> 4) * 8;
    const int b_n_off   = ((lane >> 4) & 1) * 8 + (lane & 7);
    const int b_k_off   = ((lane >> 3) & 1) * 8;

    #pragma unroll 1
    for (int qi = 0; qi < 2; qi++) {
        const int qt = (qi == 0) ? (2 * gridDim.x - 1 - blockIdx.x)
                                 : blockIdx.x;
        const int q0 = qt * 64;
        const int T = qt + 1;

        load_qk_tile(sQ_a, Qp, q0);
        issue_stage(0, 0);
        cp_commit();
        if (T > 1) issue_stage(1, 1);
        cp_commit();

        uint32_t qf[4][4];
        float oacc[8][4] = {};
        float sum_lo = 0.f, sum_hi = 0.f;

        int cur = 0;
        for (int t = 0; t < T; t++) {
            if (t == 0) {
                cp_wait_group<1>();
                __syncthreads();
                #pragma unroll
                for (int ks = 0; ks < 4; ks++) {
                    ldmatrix_x4(qf[ks],
                        sQ_a + (wm + a_row_off) * AT_ROW
                             + (ks * 16 + a_k_off) * 2);
                }
            } else if (t + 1 < T) {
                cp_wait_group<1>();
                __syncthreads();
            } else {
                cp_wait_group<0>();
                __syncthreads();
            }

            const uint32_t sK = stage_addr(cur, 0);
            const uint32_t sV = stage_addr(cur, 1);

            // ---- QK^T (scores in log2 scale via Q pre-scale) ----
            float sacc[8][4] = {};
            #pragma unroll
            for (int ks = 0; ks < 4; ks++) {
                uint32_t kf[4][4];
                #pragma unroll
                for (int ng = 0; ng < 4; ng++) {
                    ldmatrix_x4(kf[ng],
                        sK + (ng * 16 + b_n_off) * AT_ROW
                           + (ks * 16 + b_k_off) * 2);
                }
                #pragma unroll
                for (int ng = 0; ng < 4; ng++) {
                    mma_f16(sacc[2*ng],   qf[ks], kf[ng][0], kf[ng][1]);
                    mma_f16(sacc[2*ng+1], qf[ks], kf[ng][2], kf[ng][3]);
                }
            }

            // ---- causal mask (diagonal tile only) + ex2 + rowsum ----
            if (t == T - 1) {
                const int rlo = wm + (lane >> 2);
                #pragma unroll
                for (int nt = 0; nt < 8; nt++) {
                    const int c = nt * 8 + (lane & 3) * 2;
                    if (c > rlo)         sacc[nt][0] = -1e30f;
                    if (c + 1 > rlo)     sacc[nt][1] = -1e30f;
                    if (c > rlo + 8)     sacc[nt][2] = -1e30f;
                    if (c + 1 > rlo + 8) sacc[nt][3] = -1e30f;
                }
            }
            #pragma unroll
            for (int nt = 0; nt < 8; nt++) {
                sacc[nt][0] = ex2f(sacc[nt][0]);
                sacc[nt][1] = ex2f(sacc[nt][1]);
                sacc[nt][2] = ex2f(sacc[nt][2]);
                sacc[nt][3] = ex2f(sacc[nt][3]);
                sum_lo += sacc[nt][0] + sacc[nt][1];
                sum_hi += sacc[nt][2] + sacc[nt][3];
            }

            // ---- P·V ----
            #pragma unroll
            for (int j = 0; j < 4; j++) {
                uint32_t ap[4];
                ap[0] = pack_f16x2_plain(sacc[2*j][0],   sacc[2*j][1]);
                ap[1] = pack_f16x2_plain(sacc[2*j][2],   sacc[2*j][3]);
                ap[2] = pack_f16x2_plain(sacc[2*j+1][0], sacc[2*j+1][1]);
                ap[3] = pack_f16x2_plain(sacc[2*j+1][2], sacc[2*j+1][3]);
                #pragma unroll
                for (int ng = 0; ng < 4; ng++) {
                    uint32_t vf[4];
                    ldmatrix_x4(vf,
                        sV + (ng * 16 + b_n_off) * AT_ROW
                           + (j * 16 + b_k_off) * 2);
                    mma_f16(oacc[2*ng],   ap, vf[0], vf[1]);
                    mma_f16(oacc[2*ng+1], ap, vf[2], vf[3]);
                }
            }

            __syncthreads();
            if (t + 2 < T) {
                issue_stage(t + 2, cur);
                cp_commit();
            } else if (t + 1 < T) {
                cp_commit();
            }
            cur ^= 1;
        }

        // ---- epilogue: quad-reduce rowsums, normalize, store fp16 ----
        sum_lo += __shfl_xor_sync(0xFFFFFFFFu, sum_lo, 1);
        sum_lo += __shfl_xor_sync(0xFFFFFFFFu, sum_lo, 2);
        sum_hi += __shfl_xor_sync(0xFFFFFFFFu, sum_hi, 1);
        sum_hi += __shfl_xor_sync(0xFFFFFFFFu, sum_hi, 2);
        const float inv_lo = 1.0f / sum_lo;
        const float inv_hi = 1.0f / sum_hi;

        const int row_lo = q0 + wm + (lane >> 2);
        #pragma unroll
        for (int nt = 0; nt < 8; nt++) {
            const int d = nt * 8 + (lane & 3) * 2;
            const size_t off0 = (size_t)(b * Sc + row_lo) * Ec + h * Dc + d;
            const size_t off1 = off0 + (size_t)8 * Ec;
            *(uint32_t*)(Yp + off0) =
                pack_f16x2_plain(oacc[nt][0] * inv_lo, oacc[nt][1] * inv_lo);
            *(uint32_t*)(Yp + off1) =
                pack_f16x2_plain(oacc[nt][2] * inv_hi, oacc[nt][3] * inv_hi);
        }
    }
}

// ---------------------------------------------------------------------------
extern "C" void kernel_launch(void* const* d_in, const int* in_sizes, int n_in,
                              void* d_out, int out_size) {
    const float* x      = (const float*)d_in[0];
    const float* W_attn = (const float*)d_in[1];
    const float* b_attn = (const float*)d_in[2];
    const float* W_proj = (const float*)d_in[3];
    const float* b_proj = (const float*)d_in[4];
    float* out = (float*)d_out;

    __half *Xp, *Bp, *Bp2, *Yp, *Qp, *Kp, *Vtp;
    cudaGetSymbolAddress((void**)&Xp, g_Xp);
    cudaGetSymbolAddress((void**)&Bp, g_Bp);
    cudaGetSymbolAddress((void**)&Bp2, g_Bp2);
    cudaGetSymbolAddress((void**)&Yp, g_Yp);
    cudaGetSymbolAddress((void**)&Qp, g_Qp);
    cudaGetSymbolAddress((void**)&Kp, g_Kp);
    cudaGetSymbolAddress((void**)&Vtp, g_Vtp);

    cudaFuncSetAttribute(gemm_mma_kernel<0>,
                         cudaFuncAttributeMaxDynamicSharedMemorySize, GEMM_SMEM);
    cudaFuncSetAttribute(gemm_mma_kernel<1>,
                         cudaFuncAttributeMaxDynamicSharedMemorySize, GEMM_SMEM);
    cudaFuncSetAttribute(attn_mma_kernel,
                         cudaFuncAttributeMaxDynamicSharedMemorySize,
                         ATT_SMEM_BYTES);

    // 1) fused prep
    {
        prep_kernel<<<NB_CVT + NB_TA + NB_TP, 256>>>(x, W_attn, W_proj,
                                                     Xp, Bp, Bp2);
    }
    // 2) QKV GEMM (128x64 tiles), fused epilogue -> attention operands
    {
        dim3 grid(3 * Ec / GBN, MROWS / GBM);  // (48, 32)
        gemm_mma_kernel<1><<<grid, 128, GEMM_SMEM>>>(Xp, Bp, b_attn,
                                                     nullptr, 3 * Ec, Ec,
                                                     Qp, Kp, Vtp);
    }
    // 3) attention (paired q-tiles, balanced single wave) -> fp16 Yp
    {
        dim3 grid(Sc / 128, BH);  // (16, 32)
        attn_mma_kernel<<<grid, 128, ATT_SMEM_BYTES>>>(Qp, Kp, Vtp, Yp);
    }
    // 4) Proj GEMM (128x64 tiles) -> fp32 out
    {
        dim3 grid(Ec / GBN, MROWS / GBM);  // (16, 32)
        gemm_mma_kernel<0><<<grid, 128, GEMM_SMEM>>>(Yp, Bp2, b_proj,
                                                     out, Ec, Ec,
                                                     nullptr, nullptr, nullptr);
    }
}

// round 17
// speedup vs baseline: 1.4113x; 1.0155x over previous
#include <cuda_runtime.h>
#include <cuda_fp16.h>
#include <cstdint>
#include <math.h>

// Problem constants
constexpr int Bc = 2, Sc = 2048, Ec = 1024, Hc = 16, Dc = 64;
constexpr int MROWS = Bc * Sc;  // 4096
constexpr int BH = Bc * Hc;     // 32

// ---------------------------------------------------------------------------
// Scratch (device globals: allocation-free). All plain fp16.
// ---------------------------------------------------------------------------
__device__ __half g_Xp[(size_t)MROWS * Ec];    // x plain fp16 (QKV A)
__device__ __half g_Bp[(size_t)3 * Ec * Ec];   // W_attn^T plain fp16
__device__ __half g_Bp2[(size_t)Ec * Ec];      // W_proj^T plain fp16
__device__ __half g_Yp[(size_t)MROWS * Ec];    // attention out (proj A)
// Attention operands: Q (pre-scaled 0.125*log2e), K, V^T — all plain fp16
__device__ __half g_Qp[(size_t)BH * Sc * Dc];
__device__ __half g_Kp[(size_t)BH * Sc * Dc];
__device__ __half g_Vtp[(size_t)BH * Dc * Sc];

// ---------------------------------------------------------------------------
// PTX helpers (sm_80-class base features — safe under compute_103)
// ---------------------------------------------------------------------------
__device__ __forceinline__ uint32_t smem_to_u32(const void* smem_ptr) {
    uint32_t addr;
    asm("{ .reg .u64 tmp; cvta.to.shared.u64 tmp, %1; cvt.u32.u64 %0, tmp; }"
        : "=r"(addr) : "l"(smem_ptr));
    return addr;
}

__device__ __forceinline__ void cp_async16(uint32_t smem_addr, const void* gptr) {
    asm volatile("cp.async.cg.shared.global [%0], [%1], 16;\n"
                 :: "r"(smem_addr), "l"(gptr));
}
__device__ __forceinline__ void cp_commit() {
    asm volatile("cp.async.commit_group;\n" ::: "memory");
}
template <int N>
__device__ __forceinline__ void cp_wait_group() {
    asm volatile("cp.async.wait_group %0;\n" :: "n"(N) : "memory");
}

__device__ __forceinline__ void ldmatrix_x4(uint32_t* r, uint32_t addr) {
    asm volatile("ldmatrix.sync.aligned.m8n8.x4.shared.b16 {%0,%1,%2,%3}, [%4];"
                 : "=r"(r[0]), "=r"(r[1]), "=r"(r[2]), "=r"(r[3]) : "r"(addr));
}

__device__ __forceinline__ void mma_f16(float* c, const uint32_t* a,
                                        uint32_t b0, uint32_t b1) {
    asm volatile(
        "mma.sync.aligned.m16n8k16.row.col.f32.f16.f16.f32 "
        "{%0,%1,%2,%3}, {%4,%5,%6,%7}, {%8,%9}, {%0,%1,%2,%3};"
        : "+f"(c[0]), "+f"(c[1]), "+f"(c[2]), "+f"(c[3])
        : "r"(a[0]), "r"(a[1]), "r"(a[2]), "r"(a[3]), "r"(b0), "r"(b1));
}

__device__ __forceinline__ uint32_t pack_f16x2_plain(float p0, float p1) {
    __half2 h2 = __floats2half2_rn(p0, p1);   // p0 -> low half
    return *reinterpret_cast<uint32_t*>(&h2);
}

// Raw exp2 (no pre-multiply; log2e folded into Q pre-scale)
__device__ __forceinline__ float ex2f(float x) {
    float r;
    asm("ex2.approx.f32 %0, %1;" : "=f"(r) : "f"(x));
    return r;
}

// ---------------------------------------------------------------------------
// Fused prep kernel (vectorized x convert + both W transposes, one launch)
// ---------------------------------------------------------------------------
constexpr int NB_CVT = (MROWS * Ec) / (256 * 4);    // 4096
constexpr int NB_TA  = (3 * Ec / 32) * (Ec / 32);   // 3072
constexpr int NB_TP  = (Ec / 32) * (Ec / 32);       // 1024

__global__ __launch_bounds__(256)
void prep_kernel(const float* __restrict__ x,
                 const float* __restrict__ W_attn,
                 const float* __restrict__ W_proj,
                 __half* __restrict__ Xp,
                 __half* __restrict__ Bp,
                 __half* __restrict__ Bp2) {
    const int bid = blockIdx.x;
    const int t   = threadIdx.x;
    if (bid < NB_CVT) {
        const int i = (bid * 256 + t) * 4;
        float4 v = *(const float4*)(x + i);
        uint32_t lo = pack_f16x2_plain(v.x, v.y);
        uint32_t hi = pack_f16x2_plain(v.z, v.w);
        *(uint2*)(Xp + i) = make_uint2(lo, hi);
        return;
    }
    __shared__ float ts[32][33];
    const float* W;
    __half* Bt;
    int K = Ec, N, bx, by;
    if (bid < NB_CVT + NB_TA) {
        const int idx = bid - NB_CVT;
        W = W_attn; Bt = Bp; N = 3 * Ec;
        bx = idx % (3 * Ec / 32); by = idx / (3 * Ec / 32);
    } else {
        const int idx = bid - NB_CVT - NB_TA;
        W = W_proj; Bt = Bp2; N = Ec;
        bx = idx % (Ec / 32); by = idx / (Ec / 32);
    }
    const int k0 = by * 32;
    const int n0 = bx * 32;
    const int tx = t & 31;
    const int ty = t >> 5;
    #pragma unroll
    for (int i = 0; i < 4; i++)
        ts[ty + i * 8][tx] = W[(size_t)(k0 + ty + i * 8) * N + n0 + tx];
    __syncthreads();
    #pragma unroll
    for (int i = 0; i < 4; i++) {
        float v = ts[tx][ty + i * 8];
        Bt[(size_t)(n0 + ty + i * 8) * K + k0 + tx] = __float2half_rn(v);
    }
}

// ---------------------------------------------------------------------------
// HMMA plain-fp16 GEMM (fp32 accumulate), BK=64, 2-stage cp.async.
// 128 threads / 128x64 tile (4 warps, warp tile 32x64).
// MODE 0: C=fp32 (+bias). MODE 1: QKV-fused epilogue (fp16 Q/K/Vt);
// Q pre-scale = 0.125 * log2(e) so attention can use raw ex2.
// ---------------------------------------------------------------------------
constexpr int GBM = 128, GBN = 64, GBK = 64;
constexpr int G_PITCH   = 144;
constexpr int G_ATILE_B = 128 * G_PITCH;            // 18432
constexpr int G_BTILE_B = 64 * G_PITCH;             // 9216
constexpr int G_STAGE_B = G_ATILE_B + G_BTILE_B;    // 27648
constexpr int GEMM_SMEM = 2 * G_STAGE_B;            // 55296

__device__ __constant__ float kQScale = 0.125f * 1.44269504088896341f;

template <int MODE>
__global__ __launch_bounds__(128, 4)
void gemm_mma_kernel(const __half* __restrict__ Ap,
                     const __half* __restrict__ Bp,
                     const float* __restrict__ bias,
                     float* __restrict__ C,
                     int N, int K,
                     __half* __restrict__ Qp,
                     __half* __restrict__ Kp,
                     __half* __restrict__ Vtp) {
    extern __shared__ __align__(128) char gsm[];
    const uint32_t smb = smem_to_u32(gsm);

    const int tid  = threadIdx.x;
    const int wid  = tid >> 5;
    const int lane = tid & 31;
    const int m0 = blockIdx.y * GBM;
    const int n0 = blockIdx.x * GBN;
    const int wm = wid * 32;

    const int kiters = K / GBK;  // 16

    float acc[2][8][4] = {};

    const int a_row_off = lane & 15;
    const int a_k_off   = (lane >> 4) * 8;
    const int b_n_off   = ((lane >> 4) & 1) * 8 + (lane & 7);
    const int b_k_off   = ((lane >> 3) & 1) * 8;

    auto issue_load = [&](int it, int stage) {
        const int kc = it * GBK;
        const uint32_t sb = smb + stage * G_STAGE_B;
        #pragma unroll
        for (int c = 0; c < 8; c++) {
            const int chunk = tid + c * 128;
            const int row = chunk >> 3;
            const int c16 = chunk & 7;
            cp_async16(sb + row * G_PITCH + c16 * 16,
                       Ap + (size_t)(m0 + row) * K + kc + c16 * 8);
        }
        #pragma unroll
        for (int c = 0; c < 4; c++) {
            const int chunk = tid + c * 128;
            const int row = chunk >> 3;
            const int c16 = chunk & 7;
            cp_async16(sb + G_ATILE_B + row * G_PITCH + c16 * 16,
                       Bp + (size_t)(n0 + row) * K + kc + c16 * 8);
        }
    };

    issue_load(0, 0);
    cp_commit();

    int cur = 0;
    for (int it = 0; it < kiters; it++) {
        if (it + 1 < kiters) {
            issue_load(it + 1, cur ^ 1);
            cp_commit();
            cp_wait_group<1>();
        } else {
            cp_wait_group<0>();
        }
        __syncthreads();

        const uint32_t sb = smb + cur * G_STAGE_B;
        #pragma unroll
        for (int ks = 0; ks < 4; ks++) {
            const int k0 = ks * 16;
            uint32_t af[2][4], bf[4][4];
            #pragma unroll
            for (int mt = 0; mt < 2; mt++) {
                ldmatrix_x4(af[mt], sb
                            + (wm + mt * 16 + a_row_off) * G_PITCH
                            + (k0 + a_k_off) * 2);
            }
            #pragma unroll
            for (int ng = 0; ng < 4; ng++) {
                ldmatrix_x4(bf[ng], sb + G_ATILE_B
                            + (ng * 16 + b_n_off) * G_PITCH
                            + (k0 + b_k_off) * 2);
            }
            #pragma unroll
            for (int mt = 0; mt < 2; mt++) {
                #pragma unroll
                for (int ng = 0; ng < 4; ng++) {
                    mma_f16(acc[mt][2*ng],   af[mt], bf[ng][0], bf[ng][1]);
                    mma_f16(acc[mt][2*ng+1], af[mt], bf[ng][2], bf[ng][3]);
                }
            }
        }
        __syncthreads();
        cur ^= 1;
    }

    if (MODE == 0) {
        #pragma unroll
        for (int mt = 0; mt < 2; mt++) {
            const int row = m0 + wm + mt * 16 + (lane >> 2);
            #pragma unroll
            for (int nt = 0; nt < 8; nt++) {
                const int col = n0 + nt * 8 + (lane & 3) * 2;
                const float b0 = bias[col], b1 = bias[col + 1];
                float2 o0 = {acc[mt][nt][0] + b0, acc[mt][nt][1] + b1};
                float2 o1 = {acc[mt][nt][2] + b0, acc[mt][nt][3] + b1};
                *(float2*)(C + (size_t)row * N + col) = o0;
                *(float2*)(C + (size_t)(row + 8) * N + col) = o1;
            }
        }
    } else {
        const int sec = n0 >> 10;        // 0=Q, 1=K, 2=V
        const int b   = m0 >> 11;
        const int s0t = m0 & 2047;
        if (sec < 2) {
            __half* Tp = (sec == 0) ? Qp : Kp;
            const float scale = (sec == 0) ? kQScale : 1.0f;
            #pragma unroll
            for (int mt = 0; mt < 2; mt++) {
                const int s = s0t + wm + mt * 16 + (lane >> 2);
                #pragma unroll
                for (int nt = 0; nt < 8; nt++) {
                    const int col = n0 + nt * 8 + (lane & 3) * 2;
                    const int e = col & 1023;
                    const int h = e >> 6, d = e & 63;
                    const size_t rowb = (size_t)(b * Hc + h) * Sc;
                    const float bb0 = bias[col], bb1 = bias[col + 1];
                    *(uint32_t*)(Tp + (rowb + s) * Dc + d) =
                        pack_f16x2_plain((acc[mt][nt][0] + bb0) * scale,
                                         (acc[mt][nt][1] + bb1) * scale);
                    *(uint32_t*)(Tp + (rowb + s + 8) * Dc + d) =
                        pack_f16x2_plain((acc[mt][nt][2] + bb0) * scale,
                                         (acc[mt][nt][3] + bb1) * scale);
                }
            }
        } else {
            // V: fp32+bias staged in smem [128][65], transposed fp16 writes
            float* smT = (float*)gsm;
            #pragma unroll
            for (int mt = 0; mt < 2; mt++) {
                const int r = wm + mt * 16 + (lane >> 2);
                #pragma unroll
                for (int nt = 0; nt < 8; nt++) {
                    const int c = nt * 8 + (lane & 3) * 2;
                    const int col = n0 + c;
                    const float bb0 = bias[col], bb1 = bias[col + 1];
                    smT[r * 65 + c]           = acc[mt][nt][0] + bb0;
                    smT[r * 65 + c + 1]       = acc[mt][nt][1] + bb1;
                    smT[(r + 8) * 65 + c]     = acc[mt][nt][2] + bb0;
                    smT[(r + 8) * 65 + c + 1] = acc[mt][nt][3] + bb1;
                }
            }
            __syncthreads();
            const int c  = tid & 63;
            const int sh = (tid >> 6) * 64;
            const int e  = (n0 + c) & 1023;
            const int h  = e >> 6, d = e & 63;
            const size_t vbase = ((size_t)(b * Hc + h) * Dc + d) * Sc + s0t + sh;
            #pragma unroll
            for (int s = 0; s < 64; s += 2) {
                *(uint32_t*)(Vtp + vbase + s) =
                    pack_f16x2_plain(smT[(sh + s) * 65 + c],
                                     smT[(sh + s + 1) * 65 + c]);
            }
        }
    }
}

// ---------------------------------------------------------------------------
// Tensor-core causal flash attention, all plain fp16 (fp32 accumulate).
// 256 threads / 8 warps, Q-tile 128 (1x16-row m-tile per warp -> identical
// per-warp register profile as the 4-warp version). K/V tiles feed 128 rows
// -> K/V traffic and load-issue halve. Q pre-scaled by 0.125*log2e -> ex2.
// Q-TILE PAIRING: CTA bx does q-tiles {15-bx, bx}; T(qt)=2qt+2 -> exactly
// 34 ktiles per CTA; grid 8x32 = 256 CTAs = one balanced wave at 2 CTAs/SM.
// ---------------------------------------------------------------------------
constexpr int AT_ROW = 144;
constexpr int AT_KTILE_B = 64 * AT_ROW;        // 9216
constexpr int AT_QTILE_B = 128 * AT_ROW;       // 18432
// layout: Q (128 rows), 2 stages x {K, V}
constexpr int ATT_SMEM_BYTES = AT_QTILE_B + 4 * AT_KTILE_B;  // 55296

__global__ __launch_bounds__(256, 2)
void attn_mma_kernel(const __half* __restrict__ Qp,
                     const __half* __restrict__ Kp,
                     const __half* __restrict__ Vtp,
                     __half* __restrict__ Yp) {
    extern __shared__ __half smf[];
    const uint32_t smb = smem_to_u32(smf);

    const int bh = blockIdx.y;
    const int b  = bh >> 4;
    const int h  = bh & 15;
    const int tid  = threadIdx.x;
    const int wid  = tid >> 5;
    const int lane = tid & 31;
    const int wm   = wid * 16;     // 8 warps x 16 rows = 128

    const size_t bhQK = (size_t)bh * Sc * Dc;
    const size_t bhVT = (size_t)bh * Dc * Sc;

    const uint32_t sQ_a = smb;
    auto stage_addr = [&](int buf, int t) -> uint32_t {
        return smb + AT_QTILE_B + (buf * 2 + t) * AT_KTILE_B;
    };

    // Q: 128 rows x 8 x16B = 1024 chunks, 4/thread
    auto load_q_tile = [&](int s0) {
        #pragma unroll
        for (int i = 0; i < 4; i++) {
            const int idx = tid + i * 256;
            const int row = idx >> 3;
            const int c16 = idx & 7;
            cp_async16(sQ_a + row * AT_ROW + c16 * 16,
                       Qp + bhQK + (size_t)(s0 + row) * Dc + c16 * 8);
        }
    };
    // K: 64 rows x 8 = 512 chunks, 2/thread
    auto load_k_tile = [&](uint32_t sa, int kb) {
        #pragma unroll
        for (int i = 0; i < 2; i++) {
            const int idx = tid + i * 256;
            const int row = idx >> 3;
            const int c16 = idx & 7;
            cp_async16(sa + row * AT_ROW + c16 * 16,
                       Kp + bhQK + (size_t)(kb + row) * Dc + c16 * 8);
        }
    };
    auto load_vt_tile = [&](uint32_t sa, int kb) {
        #pragma unroll
        for (int i = 0; i < 2; i++) {
            const int idx = tid + i * 256;
            const int row = idx >> 3;          // d
            const int c16 = idx & 7;
            cp_async16(sa + row * AT_ROW + c16 * 16,
                       Vtp + bhVT + (size_t)row * Sc + kb + c16 * 8);
        }
    };
    auto issue_stage = [&](int t, int buf) {
        const int kb = t * 64;
        load_k_tile(stage_addr(buf, 0), kb);
        load_vt_tile(stage_addr(buf, 1), kb);
    };

    const int a_row_off = lane & 15;
    const int a_k_off   = (lane >> 4) * 8;
    const int b_n_off   = ((lane >> 4) & 1) * 8 + (lane & 7);
    const int b_k_off   = ((lane >> 3) & 1) * 8;

    #pragma unroll 1
    for (int qi = 0; qi < 2; qi++) {
        const int qt = (qi == 0) ? (2 * gridDim.x - 1 - blockIdx.x)
                                 : blockIdx.x;
        const int q0 = qt * 128;
        const int T = 2 * qt + 2;    // always >= 2

        load_q_tile(q0);
        issue_stage(0, 0);
        cp_commit();
        issue_stage(1, 1);
        cp_commit();

        uint32_t qf[4][4];
        float oacc[8][4] = {};
        float sum_lo = 0.f, sum_hi = 0.f;

        int cur = 0;
        for (int t = 0; t < T; t++) {
            if (t == 0) {
                cp_wait_group<1>();
                __syncthreads();
                #pragma unroll
                for (int ks = 0; ks < 4; ks++) {
                    ldmatrix_x4(qf[ks],
                        sQ_a + (wm + a_row_off) * AT_ROW
                             + (ks * 16 + a_k_off) * 2);
                }
            } else if (t + 1 < T) {
                cp_wait_group<1>();
                __syncthreads();
            } else {
                cp_wait_group<0>();
                __syncthreads();
            }

            const uint32_t sK = stage_addr(cur, 0);
            const uint32_t sV = stage_addr(cur, 1);

            // ---- QK^T (scores in log2 scale via Q pre-scale) ----
            float sacc[8][4] = {};
            #pragma unroll
            for (int ks = 0; ks < 4; ks++) {
                uint32_t kf[4][4];
                #pragma unroll
                for (int ng = 0; ng < 4; ng++) {
                    ldmatrix_x4(kf[ng],
                        sK + (ng * 16 + b_n_off) * AT_ROW
                           + (ks * 16 + b_k_off) * 2);
                }
                #pragma unroll
                for (int ng = 0; ng < 4; ng++) {
                    mma_f16(sacc[2*ng],   qf[ks], kf[ng][0], kf[ng][1]);
                    mma_f16(sacc[2*ng+1], qf[ks], kf[ng][2], kf[ng][3]);
                }
            }

            // ---- causal mask (last two ktiles intersect diagonal) ----
            const int kb = t * 64;
            if (t + 2 >= T) {
                const int r0 = q0 + wm + (lane >> 2);
                #pragma unroll
                for (int nt = 0; nt < 8; nt++) {
                    const int key = kb + nt * 8 + (lane & 3) * 2;
                    if (key > r0)         sacc[nt][0] = -1e30f;
                    if (key + 1 > r0)     sacc[nt][1] = -1e30f;
                    if (key > r0 + 8)     sacc[nt][2] = -1e30f;
                    if (key + 1 > r0 + 8) sacc[nt][3] = -1e30f;
                }
            }
            #pragma unroll
            for (int nt = 0; nt < 8; nt++) {
                sacc[nt][0] = ex2f(sacc[nt][0]);
                sacc[nt][1] = ex2f(sacc[nt][1]);
                sacc[nt][2] = ex2f(sacc[nt][2]);
                sacc[nt][3] = ex2f(sacc[nt][3]);
                sum_lo += sacc[nt][0] + sacc[nt][1];
                sum_hi += sacc[nt][2] + sacc[nt][3];
            }

            // ---- P·V ----
            #pragma unroll
            for (int j = 0; j < 4; j++) {
                uint32_t ap[4];
                ap[0] = pack_f16x2_plain(sacc[2*j][0],   sacc[2*j][1]);
                ap[1] = pack_f16x2_plain(sacc[2*j][2],   sacc[2*j][3]);
                ap[2] = pack_f16x2_plain(sacc[2*j+1][0], sacc[2*j+1][1]);
                ap[3] = pack_f16x2_plain(sacc[2*j+1][2], sacc[2*j+1][3]);
                #pragma unroll
                for (int ng = 0; ng < 4; ng++) {
                    uint32_t vf[4];
                    ldmatrix_x4(vf,
                        sV + (ng * 16 + b_n_off) * AT_ROW
                           + (j * 16 + b_k_off) * 2);
                    mma_f16(oacc[2*ng],   ap, vf[0], vf[1]);
                    mma_f16(oacc[2*ng+1], ap, vf[2], vf[3]);
                }
            }

            __syncthreads();
            if (t + 2 < T) {
                issue_stage(t + 2, cur);
                cp_commit();
            } else if (t + 1 < T) {
                cp_commit();
            }
            cur ^= 1;
        }

        // ---- epilogue: quad-reduce rowsums, normalize, store fp16 ----
        sum_lo += __shfl_xor_sync(0xFFFFFFFFu, sum_lo, 1);
        sum_lo += __shfl_xor_sync(0xFFFFFFFFu, sum_lo, 2);
        sum_hi += __shfl_xor_sync(0xFFFFFFFFu, sum_hi, 1);
        sum_hi += __shfl_xor_sync(0xFFFFFFFFu, sum_hi, 2);
        const float inv_lo = 1.0f / sum_lo;
        const float inv_hi = 1.0f / sum_hi;

        const int row_lo = q0 + wm + (lane >> 2);
        #pragma unroll
        for (int nt = 0; nt < 8; nt++) {
            const int d = nt * 8 + (lane & 3) * 2;
            const size_t off0 = (size_t)(b * Sc + row_lo) * Ec + h * Dc + d;
            const size_t off1 = off0 + (size_t)8 * Ec;
            *(uint32_t*)(Yp + off0) =
                pack_f16x2_plain(oacc[nt][0] * inv_lo, oacc[nt][1] * inv_lo);
            *(uint32_t*)(Yp + off1) =
                pack_f16x2_plain(oacc[nt][2] * inv_hi, oacc[nt][3] * inv_hi);
        }
    }
}

// ---------------------------------------------------------------------------
extern "C" void kernel_launch(void* const* d_in, const int* in_sizes, int n_in,
                              void* d_out, int out_size) {
    const float* x      = (const float*)d_in[0];
    const float* W_attn = (const float*)d_in[1];
    const float* b_attn = (const float*)d_in[2];
    const float* W_proj = (const float*)d_in[3];
    const float* b_proj = (const float*)d_in[4];
    float* out = (float*)d_out;

    __half *Xp, *Bp, *Bp2, *Yp, *Qp, *Kp, *Vtp;
    cudaGetSymbolAddress((void**)&Xp, g_Xp);
    cudaGetSymbolAddress((void**)&Bp, g_Bp);
    cudaGetSymbolAddress((void**)&Bp2, g_Bp2);
    cudaGetSymbolAddress((void**)&Yp, g_Yp);
    cudaGetSymbolAddress((void**)&Qp, g_Qp);
    cudaGetSymbolAddress((void**)&Kp, g_Kp);
    cudaGetSymbolAddress((void**)&Vtp, g_Vtp);

    cudaFuncSetAttribute(gemm_mma_kernel<0>,
                         cudaFuncAttributeMaxDynamicSharedMemorySize, GEMM_SMEM);
    cudaFuncSetAttribute(gemm_mma_kernel<1>,
                         cudaFuncAttributeMaxDynamicSharedMemorySize, GEMM_SMEM);
    cudaFuncSetAttribute(attn_mma_kernel,
                         cudaFuncAttributeMaxDynamicSharedMemorySize,
                         ATT_SMEM_BYTES);

    // 1) fused prep
    {
        prep_kernel<<<NB_CVT + NB_TA + NB_TP, 256>>>(x, W_attn, W_proj,
                                                     Xp, Bp, Bp2);
    }
    // 2) QKV GEMM (128x64 tiles), fused epilogue -> attention operands
    {
        dim3 grid(3 * Ec / GBN, MROWS / GBM);  // (48, 32)
        gemm_mma_kernel<1><<<grid, 128, GEMM_SMEM>>>(Xp, Bp, b_attn,
                                                     nullptr, 3 * Ec, Ec,
                                                     Qp, Kp, Vtp);
    }
    // 3) attention (Q-tile 128, paired, balanced single wave) -> fp16 Yp
    {
        dim3 grid(Sc / 256, BH);  // (8, 32) — 256 CTAs, 34 ktiles each
        attn_mma_kernel<<<grid, 256, ATT_SMEM_BYTES>>>(Qp, Kp, Vtp, Yp);
    }
    // 4) Proj GEMM (128x64 tiles) -> fp32 out
    {
        dim3 grid(Ec / GBN, MROWS / GBM);  // (16, 32)
        gemm_mma_kernel<0><<<grid, 128, GEMM_SMEM>>>(Yp, Bp2, b_proj,
                                                     out, Ec, Ec,
                                                     nullptr, nullptr, nullptr);
    }
}